// round 9
// baseline (speedup 1.0000x reference)
#include <cuda_runtime.h>

// Problem dims
#define NB 1000
#define NI 784
#define NR 256
#define NO 10

#define ALPHA 0.8f
#define KAPPA 0.8f

#define NSPLIT 9           // gemm split-K count (chunks of 128 over K=1040)

// ---------------- scratch (__device__ globals; no allocation) ----------------
__device__ float g_vpre_p[NSPLIT * NB * NR];  // split-K partials (no atomics)
__device__ float g_kL  [NB * NR];
__device__ float g_Lh  [NB * NR];
__device__ float g_Fazn[NB * NR];
__device__ float g_Fkzn[NB * NR];
__device__ float g_Faxn[NB * NI];
__device__ float g_err [NB * NO];

// ================= PREP KERNEL =================
// blocks [0,288): vpre split-K GEMM, 128x64 tiles, 8x4 micro  (8 row x 4 col x 9 splits)
// blocks [288,352): aux — zero gw outputs + Faxn + Fazn (input-only, parallel with gemm)
#define N_GEMM 288
#define PREP_GRID 352

__global__ void __launch_bounds__(256, 4)
k_prep(const float* __restrict__ x, const float* __restrict__ z,
       const float* __restrict__ w_in, const float* __restrict__ w_rec,
       const float* __restrict__ Fax, const float* __restrict__ Faz,
       float* __restrict__ gwin, float* __restrict__ gwrec, float* __restrict__ gwout) {
    if (blockIdx.x >= N_GEMM) {
        // ---- aux role ----
        int idx = (blockIdx.x - N_GEMM) * 256 + threadIdx.x;
        const int stride = (PREP_GRID - N_GEMM) * 256;   // 16384
        const float4 zz = make_float4(0.f, 0.f, 0.f, 0.f);
        for (int i = idx; i < NR * NI / 4; i += stride) ((float4*)gwin)[i] = zz;
        for (int i = idx; i < NR * NR / 4; i += stride) ((float4*)gwrec)[i] = zz;
        for (int i = idx; i < NO * NR / 4; i += stride) ((float4*)gwout)[i] = zz;
        // Faxn = ALPHA*Fax + x   (elementwise, linear layout)
        for (int i = idx; i < NB * NI / 4; i += stride) {
            float4 f = ((const float4*)Fax)[i];
            float4 xx = ((const float4*)x)[i];
            float4 o;
            o.x = fmaf(ALPHA, f.x, xx.x); o.y = fmaf(ALPHA, f.y, xx.y);
            o.z = fmaf(ALPHA, f.z, xx.z); o.w = fmaf(ALPHA, f.w, xx.w);
            ((float4*)g_Faxn)[i] = o;
        }
        // Fazn = ALPHA*Faz + z (old z)
        for (int i = idx; i < NB * NR / 4; i += stride) {
            float4 f = ((const float4*)Faz)[i];
            float4 zo = ((const float4*)z)[i];
            float4 o;
            o.x = fmaf(ALPHA, f.x, zo.x); o.y = fmaf(ALPHA, f.y, zo.y);
            o.z = fmaf(ALPHA, f.z, zo.z); o.w = fmaf(ALPHA, f.w, zo.w);
            ((float4*)g_Fazn)[i] = o;
        }
        return;
    }
    // ---- GEMM role: vpre_p[s][b,r] = sum_{k in chunk s} A[b,k] * W[r,k] ----
    // A = [x | z] (K=1040), W = [w_in | w_rec(diag zeroed)]
    // 128(batch) x 64(rec) tile, 8x4 micro-tile, register-prefetch double-buffer.
    __shared__ __align__(16) float As[16][136];
    __shared__ __align__(16) float Ws[16][72];
    const int bi = blockIdx.x;
    const int split = bi >> 5;            // 0..8
    const int rem   = bi & 31;
    const int row0 = (rem & 7) * 128;     // batch tile
    const int col0 = (rem >> 3) * 64;     // rec-unit tile
    const int tid = threadIdx.x;
    const int tr = tid >> 4, tc = tid & 15;   // 16x16 threads; rows tr*8.., cols tc*4..
    const int kk_l = tid & 15;            // loader k-offset (coalesced across lanes)
    const int m_l  = tid >> 4;            // loader m base (+16 per l)

    const int k_begin = split * 128;
    const int k_end   = (k_begin + 128 < 1040) ? (k_begin + 128) : 1040;

    float avp[8], wvp[4];
    {
        const int k = k_begin + kk_l;
#pragma unroll
        for (int l = 0; l < 8; l++) {
            int b = row0 + m_l + l * 16;
            float av = 0.f;
            if (b < NB) av = (k < NI) ? x[b * NI + k] : z[b * NR + (k - NI)];
            avp[l] = av;
        }
#pragma unroll
        for (int l = 0; l < 4; l++) {
            int r = col0 + m_l + l * 16;
            if (k < NI) wvp[l] = w_in[r * NI + k];
            else { int kr = k - NI; wvp[l] = (kr == r) ? 0.f : w_rec[r * NR + kr]; }
        }
    }

    float acc[8][4];
#pragma unroll
    for (int i = 0; i < 8; i++)
#pragma unroll
        for (int j = 0; j < 4; j++) acc[i][j] = 0.f;

    for (int kb = k_begin; kb < k_end; kb += 16) {
        // commit prefetched tile to smem
#pragma unroll
        for (int l = 0; l < 8; l++) As[kk_l][m_l + l * 16] = avp[l];
#pragma unroll
        for (int l = 0; l < 4; l++) Ws[kk_l][m_l + l * 16] = wvp[l];
        __syncthreads();
        // issue next tile's loads (overlap with compute)
        if (kb + 16 < k_end) {
            const int k = kb + 16 + kk_l;
#pragma unroll
            for (int l = 0; l < 8; l++) {
                int b = row0 + m_l + l * 16;
                float av = 0.f;
                if (b < NB) av = (k < NI) ? x[b * NI + k] : z[b * NR + (k - NI)];
                avp[l] = av;
            }
#pragma unroll
            for (int l = 0; l < 4; l++) {
                int r = col0 + m_l + l * 16;
                if (k < NI) wvp[l] = w_in[r * NI + k];
                else { int kr = k - NI; wvp[l] = (kr == r) ? 0.f : w_rec[r * NR + kr]; }
            }
        }
#pragma unroll
        for (int kk = 0; kk < 16; kk++) {
            const float4 ra0 = *(const float4*)&As[kk][tr * 8];      // LDS.128
            const float4 ra1 = *(const float4*)&As[kk][tr * 8 + 4];  // LDS.128
            const float4 rb  = *(const float4*)&Ws[kk][tc * 4];      // LDS.128
            const float ra[8] = {ra0.x, ra0.y, ra0.z, ra0.w, ra1.x, ra1.y, ra1.z, ra1.w};
#pragma unroll
            for (int i = 0; i < 8; i++) {
                acc[i][0] = fmaf(ra[i], rb.x, acc[i][0]);
                acc[i][1] = fmaf(ra[i], rb.y, acc[i][1]);
                acc[i][2] = fmaf(ra[i], rb.z, acc[i][2]);
                acc[i][3] = fmaf(ra[i], rb.w, acc[i][3]);
            }
        }
        __syncthreads();
    }
    float* dst = g_vpre_p + (size_t)split * NB * NR;
#pragma unroll
    for (int i = 0; i < 8; i++) {
        int b = row0 + tr * 8 + i;
        if (b < NB) {
            float4 vv = make_float4(acc[i][0], acc[i][1], acc[i][2], acc[i][3]);
            *(float4*)(dst + b * NR + col0 + tc * 4) = vv;
        }
    }
}

// ---------------- per-batch fused step (Faxn/Fazn moved to prep aux) ----------------
__global__ void __launch_bounds__(256)
k_step(const float* __restrict__ v, const float* __restrict__ vo,
       const float* __restrict__ z, const float* __restrict__ Fkz,
       const float* __restrict__ w_out, const float* __restrict__ yt,
       float* __restrict__ yo_out) {
    const int b = blockIdx.x;
    const int r = threadIdx.x;
    __shared__ float s_zn[NR];
    __shared__ float s_err[NO];

    const int ir = b * NR + r;
    float vpre = 0.f;
#pragma unroll
    for (int s = 0; s < NSPLIT; s++) vpre += g_vpre_p[(size_t)s * NB * NR + ir];

    const float zb = z[ir];
    const float vn = vpre + ALPHA * v[ir] * (1.f - zb);
    const float zn = (vn > 1.f) ? 1.f : 0.f;
    s_zn[r] = zn;
    const float h = fmaxf(0.f, 1.f - fabsf(vn - 1.f));
    g_Fkzn[ir] = KAPPA * Fkz[ir] + zn;
    __syncthreads();

    // vo_new GEMV in warp 0 (lanes split r, shfl-reduce), softmax in lane 0 regs
    if (r < 32) {
        const int lane = r;
        float part[NO];
#pragma unroll
        for (int o = 0; o < NO; o++) {
            float p = 0.f;
#pragma unroll
            for (int k = 0; k < 8; k++)
                p = fmaf(s_zn[lane + 32 * k], w_out[o * NR + lane + 32 * k], p);
#pragma unroll
            for (int off = 16; off; off >>= 1) p += __shfl_xor_sync(0xffffffffu, p, off);
            part[o] = p;
        }
        if (lane == 0) {
            float vn_o[NO];
            float m = -1e30f;
#pragma unroll
            for (int o = 0; o < NO; o++) {
                vn_o[o] = KAPPA * vo[b * NO + o] + part[o];
                m = fmaxf(m, vn_o[o]);
            }
            float e[NO], s = 0.f;
#pragma unroll
            for (int o = 0; o < NO; o++) { e[o] = expf(vn_o[o] - m); s += e[o]; }
            const float inv = 1.f / s;
#pragma unroll
            for (int o = 0; o < NO; o++) {
                const float yo = e[o] * inv;
                yo_out[b * NO + o] = yo;
                const float er = yo - yt[b * NO + o];
                s_err[o] = er;
                g_err[b * NO + o] = er;
            }
        }
    }
    __syncthreads();

    float L = 0.f;
#pragma unroll
    for (int o = 0; o < NO; o++) L = fmaf(s_err[o], w_out[o * NR + r], L);
    g_kL[ir] = KAPPA * L;
    g_Lh[ir] = L * h;
}

// ================= MEGA KERNEL =================
// Roles (Bresenham-interleaved, period 5 = 1 special + 4 stream):
//   special: 272 outer-GEMM blocks (4 b-splits of 250) + 50 gwout   (322)
//   stream : 1024 gwin blocks + 256 gwrec blocks                    (1280)
#define N_OUTER 272
#define N_SPECIAL 322
#define N_GWIN 1024
#define N_STREAM 1280
#define MEGA_GRID 1610     // 322 periods of 5

__device__ __forceinline__ void do_outer(int oid, float* smem,
                                         float* __restrict__ gwin,
                                         float* __restrict__ gwrec) {
    // O[i,jj] = sum_b Lh[b,i] * C[b,jj],  C = [Faxn(784) | Fazn(256)]
    float (*As)[68] = (float(*)[68])smem;
    float (*Bs)[68] = (float(*)[68])(smem + 1088);
    const int split = oid / 68;            // 0..3, b-chunks of 250
    const int rem   = oid % 68;
    const int i0 = (rem & 3) * 64;
    const int j0 = (rem >> 2) * 64;
    const int kb0 = split * 250;
    const int kb1 = kb0 + 250;
    const int tid = threadIdx.x;
    const int tr = tid >> 4, tc = tid & 15;

    float acc[4][4];
#pragma unroll
    for (int i = 0; i < 4; i++)
#pragma unroll
        for (int j = 0; j < 4; j++) acc[i][j] = 0.f;

    for (int kb = kb0; kb < kb1; kb += 16) {
#pragma unroll
        for (int l = 0; l < 4; l++) {
            int idx = tid + l * 256;
            int kk = idx >> 6;
            int m  = idx & 63;       // consecutive lanes -> consecutive i/jj (coalesced)
            int k  = kb + kk;
            As[kk][m] = (k < kb1) ? g_Lh[k * NR + i0 + m] : 0.f;
            int jj = j0 + m;
            float bv = 0.f;
            if (k < kb1 && jj < 1040)
                bv = (jj < NI) ? g_Faxn[k * NI + jj] : g_Fazn[k * NR + (jj - NI)];
            Bs[kk][m] = bv;
        }
        __syncthreads();
#pragma unroll
        for (int kk = 0; kk < 16; kk++) {
            const float4 ra = *(const float4*)&As[kk][tr * 4];   // LDS.128
            const float4 rb = *(const float4*)&Bs[kk][tc * 4];   // LDS.128
            acc[0][0] = fmaf(ra.x, rb.x, acc[0][0]); acc[0][1] = fmaf(ra.x, rb.y, acc[0][1]);
            acc[0][2] = fmaf(ra.x, rb.z, acc[0][2]); acc[0][3] = fmaf(ra.x, rb.w, acc[0][3]);
            acc[1][0] = fmaf(ra.y, rb.x, acc[1][0]); acc[1][1] = fmaf(ra.y, rb.y, acc[1][1]);
            acc[1][2] = fmaf(ra.y, rb.z, acc[1][2]); acc[1][3] = fmaf(ra.y, rb.w, acc[1][3]);
            acc[2][0] = fmaf(ra.z, rb.x, acc[2][0]); acc[2][1] = fmaf(ra.z, rb.y, acc[2][1]);
            acc[2][2] = fmaf(ra.z, rb.z, acc[2][2]); acc[2][3] = fmaf(ra.z, rb.w, acc[2][3]);
            acc[3][0] = fmaf(ra.w, rb.x, acc[3][0]); acc[3][1] = fmaf(ra.w, rb.y, acc[3][1]);
            acc[3][2] = fmaf(ra.w, rb.z, acc[3][2]); acc[3][3] = fmaf(ra.w, rb.w, acc[3][3]);
        }
        __syncthreads();
    }
#pragma unroll
    for (int i = 0; i < 4; i++) {
        int row = i0 + tr * 4 + i;
#pragma unroll
        for (int j = 0; j < 4; j++) {
            int jj = j0 + tc * 4 + j;
            if (jj < NI)            atomicAdd(&gwin[row * NI + jj], acc[i][j]);
            else if (jj < NI + NR)  atomicAdd(&gwrec[row * NR + (jj - NI)], acc[i][j]);
        }
    }
}

__device__ __forceinline__ void do_gwout(int cid, float* smem, float* __restrict__ gwout) {
    float* s_err = smem;
    const int r = threadIdx.x;
    const int b0 = cid * 20;
    for (int t = r; t < 20 * NO; t += 256) s_err[t] = g_err[b0 * NO + t];
    __syncthreads();
    float acc[NO];
#pragma unroll
    for (int o = 0; o < NO; o++) acc[o] = 0.f;
    for (int bb = 0; bb < 20; bb++) {
        const float f = g_Fkzn[(b0 + bb) * NR + r];
#pragma unroll
        for (int o = 0; o < NO; o++) acc[o] = fmaf(s_err[bb * NO + o], f, acc[o]);
    }
#pragma unroll
    for (int o = 0; o < NO; o++) atomicAdd(&gwout[o * NR + r], acc[o]);
}

#define FMA4(A, C, F) \
    A.x = fmaf(C, F.x, A.x); A.y = fmaf(C, F.y, A.y); \
    A.z = fmaf(C, F.z, A.z); A.w = fmaf(C, F.w, A.w);

__device__ __forceinline__ void do_gwin(int sid, float* smem,
                                        const float* __restrict__ Fke_in,
                                        float* __restrict__ gwin) {
    float* s_kL = smem;
    const int t = threadIdx.x;
    const int i  = sid & 255;
    const int b0 = (sid >> 8) * 250;
    for (int tt = t; tt < 250; tt += 256) s_kL[tt] = g_kL[(b0 + tt) * NR + i];
    __syncthreads();
    if (t >= 196) return;

    const float4* fke = (const float4*)(Fke_in + ((size_t)b0 * NR + i) * NI) + t;
    const size_t stride = (size_t)NR * NI / 4;
    float4 a0 = make_float4(0.f, 0.f, 0.f, 0.f);
    float4 a1 = make_float4(0.f, 0.f, 0.f, 0.f);
    float4 a2 = make_float4(0.f, 0.f, 0.f, 0.f);
    float4 a3 = make_float4(0.f, 0.f, 0.f, 0.f);
#pragma unroll 1
    for (int bb = 0; bb < 248; bb += 4) {
        float4 f0 = __ldcs(fke + (size_t)(bb + 0) * stride);
        float4 f1 = __ldcs(fke + (size_t)(bb + 1) * stride);
        float4 f2 = __ldcs(fke + (size_t)(bb + 2) * stride);
        float4 f3 = __ldcs(fke + (size_t)(bb + 3) * stride);
        float c0 = s_kL[bb], c1 = s_kL[bb + 1], c2 = s_kL[bb + 2], c3 = s_kL[bb + 3];
        FMA4(a0, c0, f0) FMA4(a1, c1, f1) FMA4(a2, c2, f2) FMA4(a3, c3, f3)
    }
    {
        float4 f0 = __ldcs(fke + (size_t)248 * stride);
        float4 f1 = __ldcs(fke + (size_t)249 * stride);
        float c0 = s_kL[248], c1 = s_kL[249];
        FMA4(a0, c0, f0) FMA4(a1, c1, f1)
    }
    float* dst = gwin + i * NI + t * 4;
    atomicAdd(dst + 0, (a0.x + a1.x) + (a2.x + a3.x));
    atomicAdd(dst + 1, (a0.y + a1.y) + (a2.y + a3.y));
    atomicAdd(dst + 2, (a0.z + a1.z) + (a2.z + a3.z));
    atomicAdd(dst + 3, (a0.w + a1.w) + (a2.w + a3.w));
}

__device__ __forceinline__ void do_gwrec(int sid, float* smem,
                                         const float* __restrict__ Fke_rec,
                                         float* __restrict__ gwrec) {
    float* s_kL = smem;   // 1000 floats (4 rows x 250)
    const int t = threadIdx.x;
    const int i0 = (sid & 63) * 4;
    const int b0 = (sid >> 6) * 250;
    const int li = t >> 6;
    const int jv = t & 63;
    for (int tt = t; tt < 1000; tt += 256) {
        int lr = tt / 250, bb = tt % 250;
        s_kL[lr * 250 + bb] = g_kL[(b0 + bb) * NR + i0 + lr];
    }
    __syncthreads();

    const int i = i0 + li;
    const float4* fke = (const float4*)(Fke_rec + ((size_t)b0 * NR + i) * NR) + jv;
    const size_t stride = (size_t)NR * NR / 4;
    const float* kl = s_kL + li * 250;
    float4 a0 = make_float4(0.f, 0.f, 0.f, 0.f);
    float4 a1 = make_float4(0.f, 0.f, 0.f, 0.f);
    float4 a2 = make_float4(0.f, 0.f, 0.f, 0.f);
    float4 a3 = make_float4(0.f, 0.f, 0.f, 0.f);
#pragma unroll 1
    for (int bb = 0; bb < 248; bb += 4) {
        float4 f0 = __ldcs(fke + (size_t)(bb + 0) * stride);
        float4 f1 = __ldcs(fke + (size_t)(bb + 1) * stride);
        float4 f2 = __ldcs(fke + (size_t)(bb + 2) * stride);
        float4 f3 = __ldcs(fke + (size_t)(bb + 3) * stride);
        float c0 = kl[bb], c1 = kl[bb + 1], c2 = kl[bb + 2], c3 = kl[bb + 3];
        FMA4(a0, c0, f0) FMA4(a1, c1, f1) FMA4(a2, c2, f2) FMA4(a3, c3, f3)
    }
    {
        float4 f0 = __ldcs(fke + (size_t)248 * stride);
        float4 f1 = __ldcs(fke + (size_t)249 * stride);
        float c0 = kl[248], c1 = kl[249];
        FMA4(a0, c0, f0) FMA4(a1, c1, f1)
    }
    float* dst = gwrec + i * NR + jv * 4;
    atomicAdd(dst + 0, (a0.x + a1.x) + (a2.x + a3.x));
    atomicAdd(dst + 1, (a0.y + a1.y) + (a2.y + a3.y));
    atomicAdd(dst + 2, (a0.z + a1.z) + (a2.z + a3.z));
    atomicAdd(dst + 3, (a0.w + a1.w) + (a2.w + a3.w));
}

__global__ void __launch_bounds__(256)
k_mega(const float* __restrict__ Fke_in, const float* __restrict__ Fke_rec,
       float* __restrict__ gwin, float* __restrict__ gwrec, float* __restrict__ gwout) {
    __shared__ __align__(16) float smem[2176];
    const int p = blockIdx.x / 5;
    const int l = blockIdx.x % 5;
    if (l == 0) {
        int sid = p;
        if (sid >= N_SPECIAL) return;
        if (sid < N_OUTER) do_outer(sid, smem, gwin, gwrec);
        else               do_gwout(sid - N_OUTER, smem, gwout);
    } else {
        int sid = p * 4 + (l - 1);
        if (sid >= N_STREAM) return;
        if (sid < N_GWIN) do_gwin(sid, smem, Fke_in, gwin);
        else              do_gwrec(sid - N_GWIN, smem, Fke_rec, gwrec);
    }
}

// ---------------- launch ----------------
extern "C" void kernel_launch(void* const* d_in, const int* in_sizes, int n_in,
                              void* d_out, int out_size) {
    const float* x       = (const float*)d_in[0];
    const float* yt      = (const float*)d_in[2];
    const float* w_in    = (const float*)d_in[3];
    const float* w_rec   = (const float*)d_in[4];
    const float* w_out   = (const float*)d_in[5];
    const float* v       = (const float*)d_in[6];
    const float* vo      = (const float*)d_in[7];
    const float* z       = (const float*)d_in[8];
    const float* Faz     = (const float*)d_in[9];
    const float* Fkz     = (const float*)d_in[10];
    const float* Fax     = (const float*)d_in[11];
    const float* Fke_rec = (const float*)d_in[12];
    const float* Fke_in  = (const float*)d_in[13];

    float* out     = (float*)d_out;
    float* yo_o    = out;
    float* gwin_o  = out + NB * NO;
    float* gwrec_o = gwin_o + NR * NI;
    float* gwout_o = gwrec_o + NR * NR;

    k_prep<<<PREP_GRID, 256>>>(x, z, w_in, w_rec, Fax, Faz, gwin_o, gwrec_o, gwout_o);
    k_step<<<NB, NR>>>(v, vo, z, Fkz, w_out, yt, yo_o);
    k_mega<<<MEGA_GRID, 256>>>(Fke_in, Fke_rec, gwin_o, gwrec_o, gwout_o);
}

// round 10
// speedup vs baseline: 1.0302x; 1.0302x over previous
#include <cuda_runtime.h>

// Problem dims
#define NB 1000
#define NI 784
#define NR 256
#define NO 10

#define ALPHA 0.8f
#define KAPPA 0.8f

#define NSPLIT 17          // gemm split-K count (chunks of 64 over K=1040; last=16)

// ---------------- scratch (__device__ globals; no allocation) ----------------
__device__ float g_vpre_p[NSPLIT * NB * NR];  // split-K partials (no atomics)
__device__ float g_kL  [NB * NR];
__device__ float g_Lh  [NB * NR];
__device__ float g_Fazn[NB * NR];
__device__ float g_Fkzn[NB * NR];
__device__ float g_Faxn[NB * NI];
__device__ float g_err [NB * NO];

// ================= PREP KERNEL =================
// blocks [0,544): vpre split-K GEMM, 128x64 tiles, 8x4 micro (8 row x 4 col x 17 splits)
// blocks [544,560): zero gwin/gwrec/gwout
#define N_GEMM 544
#define PREP_GRID 560

__global__ void __launch_bounds__(256)
k_prep(const float* __restrict__ x, const float* __restrict__ z,
       const float* __restrict__ w_in, const float* __restrict__ w_rec,
       float* __restrict__ gwin, float* __restrict__ gwrec, float* __restrict__ gwout) {
    if (blockIdx.x >= N_GEMM) {
        int idx = (blockIdx.x - N_GEMM) * 256 + threadIdx.x;
        const int stride = (PREP_GRID - N_GEMM) * 256;
        const float4 zz = make_float4(0.f, 0.f, 0.f, 0.f);
        for (int i = idx; i < NR * NI / 4; i += stride) ((float4*)gwin)[i] = zz;
        for (int i = idx; i < NR * NR / 4; i += stride) ((float4*)gwrec)[i] = zz;
        for (int i = idx; i < NO * NR / 4; i += stride) ((float4*)gwout)[i] = zz;
        return;
    }
    // ---- GEMM role: vpre_p[s][b,r] = sum_{k in chunk s} A[b,k] * W[r,k] ----
    // A = [x | z] (K=1040), W = [w_in | w_rec(diag zeroed)]
    // 128(batch) x 64(rec) tile, 8x4 micro-tile, register-prefetch double-buffer.
    __shared__ __align__(16) float As[16][136];
    __shared__ __align__(16) float Ws[16][72];
    const int bi = blockIdx.x;
    const int split = bi >> 5;            // 0..16
    const int rem   = bi & 31;
    const int row0 = (rem & 7) * 128;     // batch tile
    const int col0 = (rem >> 3) * 64;     // rec-unit tile
    const int tid = threadIdx.x;
    const int tr = tid >> 4, tc = tid & 15;   // rows tr*8.., cols tc*4..
    const int kk_l = tid & 15;            // loader k-offset (coalesced across lanes)
    const int m_l  = tid >> 4;            // loader m base (+16 per l)

    const int k_begin = split * 64;
    const int k_end   = (k_begin + 64 < 1040) ? (k_begin + 64) : 1040;

    float avp[8], wvp[4];
    {
        const int k = k_begin + kk_l;
#pragma unroll
        for (int l = 0; l < 8; l++) {
            int b = row0 + m_l + l * 16;
            float av = 0.f;
            if (b < NB) av = (k < NI) ? x[b * NI + k] : z[b * NR + (k - NI)];
            avp[l] = av;
        }
#pragma unroll
        for (int l = 0; l < 4; l++) {
            int r = col0 + m_l + l * 16;
            if (k < NI) wvp[l] = w_in[r * NI + k];
            else { int kr = k - NI; wvp[l] = (kr == r) ? 0.f : w_rec[r * NR + kr]; }
        }
    }

    float acc[8][4];
#pragma unroll
    for (int i = 0; i < 8; i++)
#pragma unroll
        for (int j = 0; j < 4; j++) acc[i][j] = 0.f;

    for (int kb = k_begin; kb < k_end; kb += 16) {
        // commit prefetched tile to smem
#pragma unroll
        for (int l = 0; l < 8; l++) As[kk_l][m_l + l * 16] = avp[l];
#pragma unroll
        for (int l = 0; l < 4; l++) Ws[kk_l][m_l + l * 16] = wvp[l];
        __syncthreads();
        // issue next tile's loads (overlap with compute)
        if (kb + 16 < k_end) {
            const int k = kb + 16 + kk_l;
#pragma unroll
            for (int l = 0; l < 8; l++) {
                int b = row0 + m_l + l * 16;
                float av = 0.f;
                if (b < NB) av = (k < NI) ? x[b * NI + k] : z[b * NR + (k - NI)];
                avp[l] = av;
            }
#pragma unroll
            for (int l = 0; l < 4; l++) {
                int r = col0 + m_l + l * 16;
                if (k < NI) wvp[l] = w_in[r * NI + k];
                else { int kr = k - NI; wvp[l] = (kr == r) ? 0.f : w_rec[r * NR + kr]; }
            }
        }
#pragma unroll
        for (int kk = 0; kk < 16; kk++) {
            const float4 ra0 = *(const float4*)&As[kk][tr * 8];      // LDS.128
            const float4 ra1 = *(const float4*)&As[kk][tr * 8 + 4];  // LDS.128
            const float4 rb  = *(const float4*)&Ws[kk][tc * 4];      // LDS.128
            const float ra[8] = {ra0.x, ra0.y, ra0.z, ra0.w, ra1.x, ra1.y, ra1.z, ra1.w};
#pragma unroll
            for (int i = 0; i < 8; i++) {
                acc[i][0] = fmaf(ra[i], rb.x, acc[i][0]);
                acc[i][1] = fmaf(ra[i], rb.y, acc[i][1]);
                acc[i][2] = fmaf(ra[i], rb.z, acc[i][2]);
                acc[i][3] = fmaf(ra[i], rb.w, acc[i][3]);
            }
        }
        __syncthreads();
    }
    float* dst = g_vpre_p + (size_t)split * NB * NR;
#pragma unroll
    for (int i = 0; i < 8; i++) {
        int b = row0 + tr * 8 + i;
        if (b < NB) {
            float4 vv = make_float4(acc[i][0], acc[i][1], acc[i][2], acc[i][3]);
            *(float4*)(dst + b * NR + col0 + tc * 4) = vv;
        }
    }
}

// ---------------- per-batch fused step ----------------
__global__ void __launch_bounds__(256)
k_step(const float* __restrict__ v, const float* __restrict__ vo,
       const float* __restrict__ z, const float* __restrict__ Faz,
       const float* __restrict__ Fkz, const float* __restrict__ Fax,
       const float* __restrict__ x, const float* __restrict__ w_out,
       const float* __restrict__ yt, float* __restrict__ yo_out) {
    const int b = blockIdx.x;
    const int r = threadIdx.x;
    __shared__ float s_zn[NR];
    __shared__ float s_err[NO];

    const int ir = b * NR + r;
    float vpre = 0.f;
#pragma unroll
    for (int s = 0; s < NSPLIT; s++) vpre += g_vpre_p[(size_t)s * NB * NR + ir];

    const float zb = z[ir];
    const float vn = vpre + ALPHA * v[ir] * (1.f - zb);
    const float zn = (vn > 1.f) ? 1.f : 0.f;
    s_zn[r] = zn;
    const float h = fmaxf(0.f, 1.f - fabsf(vn - 1.f));
    g_Fazn[ir] = ALPHA * Faz[ir] + zb;
    g_Fkzn[ir] = KAPPA * Fkz[ir] + zn;

    if (r < 196) {
        const float4 fx = ((const float4*)(Fax + b * NI))[r];
        const float4 xx = ((const float4*)(x + b * NI))[r];
        float4 o;
        o.x = fmaf(ALPHA, fx.x, xx.x);
        o.y = fmaf(ALPHA, fx.y, xx.y);
        o.z = fmaf(ALPHA, fx.z, xx.z);
        o.w = fmaf(ALPHA, fx.w, xx.w);
        ((float4*)(g_Faxn + b * NI))[r] = o;
    }
    __syncthreads();

    // vo_new GEMV in warp 0 (lanes split r, shfl-reduce), softmax in lane 0 regs
    if (r < 32) {
        const int lane = r;
        float part[NO];
#pragma unroll
        for (int o = 0; o < NO; o++) {
            float p = 0.f;
#pragma unroll
            for (int k = 0; k < 8; k++)
                p = fmaf(s_zn[lane + 32 * k], w_out[o * NR + lane + 32 * k], p);
#pragma unroll
            for (int off = 16; off; off >>= 1) p += __shfl_xor_sync(0xffffffffu, p, off);
            part[o] = p;
        }
        if (lane == 0) {
            float vn_o[NO];
            float m = -1e30f;
#pragma unroll
            for (int o = 0; o < NO; o++) {
                vn_o[o] = KAPPA * vo[b * NO + o] + part[o];
                m = fmaxf(m, vn_o[o]);
            }
            float e[NO], s = 0.f;
#pragma unroll
            for (int o = 0; o < NO; o++) { e[o] = expf(vn_o[o] - m); s += e[o]; }
            const float inv = 1.f / s;
#pragma unroll
            for (int o = 0; o < NO; o++) {
                const float yo = e[o] * inv;
                yo_out[b * NO + o] = yo;
                const float er = yo - yt[b * NO + o];
                s_err[o] = er;
                g_err[b * NO + o] = er;
            }
        }
    }
    __syncthreads();

    float L = 0.f;
#pragma unroll
    for (int o = 0; o < NO; o++) L = fmaf(s_err[o], w_out[o * NR + r], L);
    g_kL[ir] = KAPPA * L;
    g_Lh[ir] = L * h;
}

// ================= MEGA KERNEL =================
// Roles (Bresenham-interleaved, period 5 = 1 special + 4 stream):
//   special: 272 outer-GEMM blocks (4 b-splits of 250) + 50 gwout   (322)
//   stream : 1024 gwin blocks + 256 gwrec blocks                    (1280)
#define N_OUTER 272
#define N_SPECIAL 322
#define N_GWIN 1024
#define N_STREAM 1280
#define MEGA_GRID 1610     // 322 periods of 5

__device__ __forceinline__ void do_outer(int oid, float* smem,
                                         float* __restrict__ gwin,
                                         float* __restrict__ gwrec) {
    // O[i,jj] = sum_b Lh[b,i] * C[b,jj],  C = [Faxn(784) | Fazn(256)]
    float (*As)[68] = (float(*)[68])smem;
    float (*Bs)[68] = (float(*)[68])(smem + 1088);
    const int split = oid / 68;            // 0..3, b-chunks of 250
    const int rem   = oid % 68;
    const int i0 = (rem & 3) * 64;
    const int j0 = (rem >> 2) * 64;
    const int kb0 = split * 250;
    const int kb1 = kb0 + 250;
    const int tid = threadIdx.x;
    const int tr = tid >> 4, tc = tid & 15;

    float acc[4][4];
#pragma unroll
    for (int i = 0; i < 4; i++)
#pragma unroll
        for (int j = 0; j < 4; j++) acc[i][j] = 0.f;

    for (int kb = kb0; kb < kb1; kb += 16) {
#pragma unroll
        for (int l = 0; l < 4; l++) {
            int idx = tid + l * 256;
            int kk = idx >> 6;
            int m  = idx & 63;       // consecutive lanes -> consecutive i/jj (coalesced)
            int k  = kb + kk;
            As[kk][m] = (k < kb1) ? g_Lh[k * NR + i0 + m] : 0.f;
            int jj = j0 + m;
            float bv = 0.f;
            if (k < kb1 && jj < 1040)
                bv = (jj < NI) ? g_Faxn[k * NI + jj] : g_Fazn[k * NR + (jj - NI)];
            Bs[kk][m] = bv;
        }
        __syncthreads();
#pragma unroll
        for (int kk = 0; kk < 16; kk++) {
            const float4 ra = *(const float4*)&As[kk][tr * 4];   // LDS.128
            const float4 rb = *(const float4*)&Bs[kk][tc * 4];   // LDS.128
            acc[0][0] = fmaf(ra.x, rb.x, acc[0][0]); acc[0][1] = fmaf(ra.x, rb.y, acc[0][1]);
            acc[0][2] = fmaf(ra.x, rb.z, acc[0][2]); acc[0][3] = fmaf(ra.x, rb.w, acc[0][3]);
            acc[1][0] = fmaf(ra.y, rb.x, acc[1][0]); acc[1][1] = fmaf(ra.y, rb.y, acc[1][1]);
            acc[1][2] = fmaf(ra.y, rb.z, acc[1][2]); acc[1][3] = fmaf(ra.y, rb.w, acc[1][3]);
            acc[2][0] = fmaf(ra.z, rb.x, acc[2][0]); acc[2][1] = fmaf(ra.z, rb.y, acc[2][1]);
            acc[2][2] = fmaf(ra.z, rb.z, acc[2][2]); acc[2][3] = fmaf(ra.z, rb.w, acc[2][3]);
            acc[3][0] = fmaf(ra.w, rb.x, acc[3][0]); acc[3][1] = fmaf(ra.w, rb.y, acc[3][1]);
            acc[3][2] = fmaf(ra.w, rb.z, acc[3][2]); acc[3][3] = fmaf(ra.w, rb.w, acc[3][3]);
        }
        __syncthreads();
    }
#pragma unroll
    for (int i = 0; i < 4; i++) {
        int row = i0 + tr * 4 + i;
#pragma unroll
        for (int j = 0; j < 4; j++) {
            int jj = j0 + tc * 4 + j;
            if (jj < NI)            atomicAdd(&gwin[row * NI + jj], acc[i][j]);
            else if (jj < NI + NR)  atomicAdd(&gwrec[row * NR + (jj - NI)], acc[i][j]);
        }
    }
}

__device__ __forceinline__ void do_gwout(int cid, float* smem, float* __restrict__ gwout) {
    float* s_err = smem;
    const int r = threadIdx.x;
    const int b0 = cid * 20;
    for (int t = r; t < 20 * NO; t += 256) s_err[t] = g_err[b0 * NO + t];
    __syncthreads();
    float acc[NO];
#pragma unroll
    for (int o = 0; o < NO; o++) acc[o] = 0.f;
    for (int bb = 0; bb < 20; bb++) {
        const float f = g_Fkzn[(b0 + bb) * NR + r];
#pragma unroll
        for (int o = 0; o < NO; o++) acc[o] = fmaf(s_err[bb * NO + o], f, acc[o]);
    }
#pragma unroll
    for (int o = 0; o < NO; o++) atomicAdd(&gwout[o * NR + r], acc[o]);
}

#define FMA4(A, C, F) \
    A.x = fmaf(C, F.x, A.x); A.y = fmaf(C, F.y, A.y); \
    A.z = fmaf(C, F.z, A.z); A.w = fmaf(C, F.w, A.w);

__device__ __forceinline__ void do_gwin(int sid, float* smem,
                                        const float* __restrict__ Fke_in,
                                        float* __restrict__ gwin) {
    float* s_kL = smem;
    const int t = threadIdx.x;
    const int i  = sid & 255;
    const int b0 = (sid >> 8) * 250;
    for (int tt = t; tt < 250; tt += 256) s_kL[tt] = g_kL[(b0 + tt) * NR + i];
    __syncthreads();
    if (t >= 196) return;

    const float4* fke = (const float4*)(Fke_in + ((size_t)b0 * NR + i) * NI) + t;
    const size_t stride = (size_t)NR * NI / 4;
    float4 a0 = make_float4(0.f, 0.f, 0.f, 0.f);
    float4 a1 = make_float4(0.f, 0.f, 0.f, 0.f);
    float4 a2 = make_float4(0.f, 0.f, 0.f, 0.f);
    float4 a3 = make_float4(0.f, 0.f, 0.f, 0.f);
#pragma unroll 1
    for (int bb = 0; bb < 248; bb += 4) {
        float4 f0 = __ldcs(fke + (size_t)(bb + 0) * stride);
        float4 f1 = __ldcs(fke + (size_t)(bb + 1) * stride);
        float4 f2 = __ldcs(fke + (size_t)(bb + 2) * stride);
        float4 f3 = __ldcs(fke + (size_t)(bb + 3) * stride);
        float c0 = s_kL[bb], c1 = s_kL[bb + 1], c2 = s_kL[bb + 2], c3 = s_kL[bb + 3];
        FMA4(a0, c0, f0) FMA4(a1, c1, f1) FMA4(a2, c2, f2) FMA4(a3, c3, f3)
    }
    {
        float4 f0 = __ldcs(fke + (size_t)248 * stride);
        float4 f1 = __ldcs(fke + (size_t)249 * stride);
        float c0 = s_kL[248], c1 = s_kL[249];
        FMA4(a0, c0, f0) FMA4(a1, c1, f1)
    }
    float* dst = gwin + i * NI + t * 4;
    atomicAdd(dst + 0, (a0.x + a1.x) + (a2.x + a3.x));
    atomicAdd(dst + 1, (a0.y + a1.y) + (a2.y + a3.y));
    atomicAdd(dst + 2, (a0.z + a1.z) + (a2.z + a3.z));
    atomicAdd(dst + 3, (a0.w + a1.w) + (a2.w + a3.w));
}

__device__ __forceinline__ void do_gwrec(int sid, float* smem,
                                         const float* __restrict__ Fke_rec,
                                         float* __restrict__ gwrec) {
    float* s_kL = smem;   // 1000 floats (4 rows x 250)
    const int t = threadIdx.x;
    const int i0 = (sid & 63) * 4;
    const int b0 = (sid >> 6) * 250;
    const int li = t >> 6;
    const int jv = t & 63;
    for (int tt = t; tt < 1000; tt += 256) {
        int lr = tt / 250, bb = tt % 250;
        s_kL[lr * 250 + bb] = g_kL[(b0 + bb) * NR + i0 + lr];
    }
    __syncthreads();

    const int i = i0 + li;
    const float4* fke = (const float4*)(Fke_rec + ((size_t)b0 * NR + i) * NR) + jv;
    const size_t stride = (size_t)NR * NR / 4;
    const float* kl = s_kL + li * 250;
    float4 a0 = make_float4(0.f, 0.f, 0.f, 0.f);
    float4 a1 = make_float4(0.f, 0.f, 0.f, 0.f);
    float4 a2 = make_float4(0.f, 0.f, 0.f, 0.f);
    float4 a3 = make_float4(0.f, 0.f, 0.f, 0.f);
#pragma unroll 1
    for (int bb = 0; bb < 248; bb += 4) {
        float4 f0 = __ldcs(fke + (size_t)(bb + 0) * stride);
        float4 f1 = __ldcs(fke + (size_t)(bb + 1) * stride);
        float4 f2 = __ldcs(fke + (size_t)(bb + 2) * stride);
        float4 f3 = __ldcs(fke + (size_t)(bb + 3) * stride);
        float c0 = kl[bb], c1 = kl[bb + 1], c2 = kl[bb + 2], c3 = kl[bb + 3];
        FMA4(a0, c0, f0) FMA4(a1, c1, f1) FMA4(a2, c2, f2) FMA4(a3, c3, f3)
    }
    {
        float4 f0 = __ldcs(fke + (size_t)248 * stride);
        float4 f1 = __ldcs(fke + (size_t)249 * stride);
        float c0 = kl[248], c1 = kl[249];
        FMA4(a0, c0, f0) FMA4(a1, c1, f1)
    }
    float* dst = gwrec + i * NR + jv * 4;
    atomicAdd(dst + 0, (a0.x + a1.x) + (a2.x + a3.x));
    atomicAdd(dst + 1, (a0.y + a1.y) + (a2.y + a3.y));
    atomicAdd(dst + 2, (a0.z + a1.z) + (a2.z + a3.z));
    atomicAdd(dst + 3, (a0.w + a1.w) + (a2.w + a3.w));
}

__global__ void __launch_bounds__(256)
k_mega(const float* __restrict__ Fke_in, const float* __restrict__ Fke_rec,
       float* __restrict__ gwin, float* __restrict__ gwrec, float* __restrict__ gwout) {
    __shared__ __align__(16) float smem[2176];
    const int p = blockIdx.x / 5;
    const int l = blockIdx.x % 5;
    if (l == 0) {
        int sid = p;
        if (sid >= N_SPECIAL) return;
        if (sid < N_OUTER) do_outer(sid, smem, gwin, gwrec);
        else               do_gwout(sid - N_OUTER, smem, gwout);
    } else {
        int sid = p * 4 + (l - 1);
        if (sid >= N_STREAM) return;
        if (sid < N_GWIN) do_gwin(sid, smem, Fke_in, gwin);
        else              do_gwrec(sid - N_GWIN, smem, Fke_rec, gwrec);
    }
}

// ---------------- launch ----------------
extern "C" void kernel_launch(void* const* d_in, const int* in_sizes, int n_in,
                              void* d_out, int out_size) {
    const float* x       = (const float*)d_in[0];
    const float* yt      = (const float*)d_in[2];
    const float* w_in    = (const float*)d_in[3];
    const float* w_rec   = (const float*)d_in[4];
    const float* w_out   = (const float*)d_in[5];
    const float* v       = (const float*)d_in[6];
    const float* vo      = (const float*)d_in[7];
    const float* z       = (const float*)d_in[8];
    const float* Faz     = (const float*)d_in[9];
    const float* Fkz     = (const float*)d_in[10];
    const float* Fax     = (const float*)d_in[11];
    const float* Fke_rec = (const float*)d_in[12];
    const float* Fke_in  = (const float*)d_in[13];

    float* out     = (float*)d_out;
    float* yo_o    = out;
    float* gwin_o  = out + NB * NO;
    float* gwrec_o = gwin_o + NR * NI;
    float* gwout_o = gwrec_o + NR * NR;

    k_prep<<<PREP_GRID, 256>>>(x, z, w_in, w_rec, gwin_o, gwrec_o, gwout_o);
    k_step<<<NB, NR>>>(v, vo, z, Faz, Fkz, Fax, x, w_out, yt, yo_o);
    k_mega<<<MEGA_GRID, 256>>>(Fke_in, Fke_rec, gwin_o, gwrec_o, gwout_o);
}

// round 11
// speedup vs baseline: 1.0330x; 1.0027x over previous
#include <cuda_runtime.h>

// Problem dims
#define NB 1000
#define NI 784
#define NR 256
#define NO 10

#define ALPHA 0.8f
#define KAPPA 0.8f

#define NSPLIT 17          // gemm split-K count (chunks of 64 over K=1040; last=16)

// ---------------- scratch (__device__ globals; no allocation) ----------------
__device__ float g_vpre_p[NSPLIT * NB * NR];  // split-K partials (no atomics)
__device__ float g_kL  [NB * NR];
__device__ float g_Lh  [NB * NR];
__device__ float g_Fazn[NB * NR];
__device__ float g_Fkzn[NB * NR];
__device__ float g_Faxn[NB * NI];
__device__ float g_err [NB * NO];

// ================= PREP KERNEL =================
// blocks [0,544): vpre split-K GEMM, 128x64 tiles, 8x4 micro, DOUBLE-BUFFERED smem
// blocks [544,608): aux — zero gw outputs + Faxn + Fazn (input-only, runs in GEMM's shadow)
#define N_GEMM 544
#define PREP_GRID 608

__global__ void __launch_bounds__(256)
k_prep(const float* __restrict__ x, const float* __restrict__ z,
       const float* __restrict__ w_in, const float* __restrict__ w_rec,
       const float* __restrict__ Fax, const float* __restrict__ Faz,
       float* __restrict__ gwin, float* __restrict__ gwrec, float* __restrict__ gwout) {
    if (blockIdx.x >= N_GEMM) {
        // ---- aux role ----
        int idx = (blockIdx.x - N_GEMM) * 256 + threadIdx.x;
        const int stride = (PREP_GRID - N_GEMM) * 256;   // 16384
        const float4 zz = make_float4(0.f, 0.f, 0.f, 0.f);
        for (int i = idx; i < NR * NI / 4; i += stride) ((float4*)gwin)[i] = zz;
        for (int i = idx; i < NR * NR / 4; i += stride) ((float4*)gwrec)[i] = zz;
        for (int i = idx; i < NO * NR / 4; i += stride) ((float4*)gwout)[i] = zz;
        // Faxn = ALPHA*Fax + x
        for (int i = idx; i < NB * NI / 4; i += stride) {
            float4 f = ((const float4*)Fax)[i];
            float4 xx = ((const float4*)x)[i];
            float4 o;
            o.x = fmaf(ALPHA, f.x, xx.x); o.y = fmaf(ALPHA, f.y, xx.y);
            o.z = fmaf(ALPHA, f.z, xx.z); o.w = fmaf(ALPHA, f.w, xx.w);
            ((float4*)g_Faxn)[i] = o;
        }
        // Fazn = ALPHA*Faz + z (old z)
        for (int i = idx; i < NB * NR / 4; i += stride) {
            float4 f = ((const float4*)Faz)[i];
            float4 zo = ((const float4*)z)[i];
            float4 o;
            o.x = fmaf(ALPHA, f.x, zo.x); o.y = fmaf(ALPHA, f.y, zo.y);
            o.z = fmaf(ALPHA, f.z, zo.z); o.w = fmaf(ALPHA, f.w, zo.w);
            ((float4*)g_Fazn)[i] = o;
        }
        return;
    }
    // ---- GEMM role: vpre_p[s][b,r] = sum_{k in chunk s} A[b,k] * W[r,k] ----
    // A = [x | z] (K=1040), W = [w_in | w_rec(diag zeroed)]
    // 128(batch) x 64(rec) tile, 8x4 micro, double-buffered smem (1 barrier/tile).
    __shared__ __align__(16) float As[2][16][136];
    __shared__ __align__(16) float Ws[2][16][72];
    const int bi = blockIdx.x;
    const int split = bi >> 5;            // 0..16
    const int rem   = bi & 31;
    const int row0 = (rem & 7) * 128;     // batch tile
    const int col0 = (rem >> 3) * 64;     // rec-unit tile
    const int tid = threadIdx.x;
    const int tr = tid >> 4, tc = tid & 15;   // rows tr*8.., cols tc*4..
    const int kk_l = tid & 15;            // loader k-offset (coalesced across lanes)
    const int m_l  = tid >> 4;            // loader m base (+16 per l)

    const int k_begin = split * 64;
    const int k_end   = (k_begin + 64 < 1040) ? (k_begin + 64) : 1040;

    float avp[8], wvp[4];
    // load tile 0 into registers, commit to buffer 0
    {
        const int k = k_begin + kk_l;
#pragma unroll
        for (int l = 0; l < 8; l++) {
            int b = row0 + m_l + l * 16;
            float av = 0.f;
            if (b < NB) av = (k < NI) ? x[b * NI + k] : z[b * NR + (k - NI)];
            avp[l] = av;
        }
#pragma unroll
        for (int l = 0; l < 4; l++) {
            int r = col0 + m_l + l * 16;
            if (k < NI) wvp[l] = w_in[r * NI + k];
            else { int kr = k - NI; wvp[l] = (kr == r) ? 0.f : w_rec[r * NR + kr]; }
        }
#pragma unroll
        for (int l = 0; l < 8; l++) As[0][kk_l][m_l + l * 16] = avp[l];
#pragma unroll
        for (int l = 0; l < 4; l++) Ws[0][kk_l][m_l + l * 16] = wvp[l];
    }
    __syncthreads();

    float acc[8][4];
#pragma unroll
    for (int i = 0; i < 8; i++)
#pragma unroll
        for (int j = 0; j < 4; j++) acc[i][j] = 0.f;

    int buf = 0;
    for (int kb = k_begin; kb < k_end; kb += 16) {
        const bool has_next = (kb + 16) < k_end;
        // issue next tile's global loads (overlap with compute below)
        if (has_next) {
            const int k = kb + 16 + kk_l;
#pragma unroll
            for (int l = 0; l < 8; l++) {
                int b = row0 + m_l + l * 16;
                float av = 0.f;
                if (b < NB) av = (k < NI) ? x[b * NI + k] : z[b * NR + (k - NI)];
                avp[l] = av;
            }
#pragma unroll
            for (int l = 0; l < 4; l++) {
                int r = col0 + m_l + l * 16;
                if (k < NI) wvp[l] = w_in[r * NI + k];
                else { int kr = k - NI; wvp[l] = (kr == r) ? 0.f : w_rec[r * NR + kr]; }
            }
        }
        // compute from current buffer
#pragma unroll
        for (int kk = 0; kk < 16; kk++) {
            const float4 ra0 = *(const float4*)&As[buf][kk][tr * 8];      // LDS.128
            const float4 ra1 = *(const float4*)&As[buf][kk][tr * 8 + 4];  // LDS.128
            const float4 rb  = *(const float4*)&Ws[buf][kk][tc * 4];      // LDS.128
            const float ra[8] = {ra0.x, ra0.y, ra0.z, ra0.w, ra1.x, ra1.y, ra1.z, ra1.w};
#pragma unroll
            for (int i = 0; i < 8; i++) {
                acc[i][0] = fmaf(ra[i], rb.x, acc[i][0]);
                acc[i][1] = fmaf(ra[i], rb.y, acc[i][1]);
                acc[i][2] = fmaf(ra[i], rb.z, acc[i][2]);
                acc[i][3] = fmaf(ra[i], rb.w, acc[i][3]);
            }
        }
        // commit next tile to the other buffer; single barrier per tile
        if (has_next) {
            const int nb = buf ^ 1;
#pragma unroll
            for (int l = 0; l < 8; l++) As[nb][kk_l][m_l + l * 16] = avp[l];
#pragma unroll
            for (int l = 0; l < 4; l++) Ws[nb][kk_l][m_l + l * 16] = wvp[l];
            __syncthreads();
            buf = nb;
        }
    }
    float* dst = g_vpre_p + (size_t)split * NB * NR;
#pragma unroll
    for (int i = 0; i < 8; i++) {
        int b = row0 + tr * 8 + i;
        if (b < NB) {
            float4 vv = make_float4(acc[i][0], acc[i][1], acc[i][2], acc[i][3]);
            *(float4*)(dst + b * NR + col0 + tc * 4) = vv;
        }
    }
}

// ---------------- per-batch fused step (Faxn/Fazn handled by prep aux) ----------------
__global__ void __launch_bounds__(256)
k_step(const float* __restrict__ v, const float* __restrict__ vo,
       const float* __restrict__ z, const float* __restrict__ Fkz,
       const float* __restrict__ w_out, const float* __restrict__ yt,
       float* __restrict__ yo_out) {
    const int b = blockIdx.x;
    const int r = threadIdx.x;
    __shared__ float s_zn[NR];
    __shared__ float s_err[NO];

    const int ir = b * NR + r;
    float vpre = 0.f;
#pragma unroll
    for (int s = 0; s < NSPLIT; s++) vpre += g_vpre_p[(size_t)s * NB * NR + ir];

    const float zb = z[ir];
    const float vn = vpre + ALPHA * v[ir] * (1.f - zb);
    const float zn = (vn > 1.f) ? 1.f : 0.f;
    s_zn[r] = zn;
    const float h = fmaxf(0.f, 1.f - fabsf(vn - 1.f));
    g_Fkzn[ir] = KAPPA * Fkz[ir] + zn;
    __syncthreads();

    // vo_new GEMV in warp 0 (lanes split r, shfl-reduce), softmax in lane 0 regs
    if (r < 32) {
        const int lane = r;
        float part[NO];
#pragma unroll
        for (int o = 0; o < NO; o++) {
            float p = 0.f;
#pragma unroll
            for (int k = 0; k < 8; k++)
                p = fmaf(s_zn[lane + 32 * k], w_out[o * NR + lane + 32 * k], p);
#pragma unroll
            for (int off = 16; off; off >>= 1) p += __shfl_xor_sync(0xffffffffu, p, off);
            part[o] = p;
        }
        if (lane == 0) {
            float vn_o[NO];
            float m = -1e30f;
#pragma unroll
            for (int o = 0; o < NO; o++) {
                vn_o[o] = KAPPA * vo[b * NO + o] + part[o];
                m = fmaxf(m, vn_o[o]);
            }
            float e[NO], s = 0.f;
#pragma unroll
            for (int o = 0; o < NO; o++) { e[o] = expf(vn_o[o] - m); s += e[o]; }
            const float inv = 1.f / s;
#pragma unroll
            for (int o = 0; o < NO; o++) {
                const float yo = e[o] * inv;
                yo_out[b * NO + o] = yo;
                const float er = yo - yt[b * NO + o];
                s_err[o] = er;
                g_err[b * NO + o] = er;
            }
        }
    }
    __syncthreads();

    float L = 0.f;
#pragma unroll
    for (int o = 0; o < NO; o++) L = fmaf(s_err[o], w_out[o * NR + r], L);
    g_kL[ir] = KAPPA * L;
    g_Lh[ir] = L * h;
}

// ================= MEGA KERNEL =================
// Roles (Bresenham-interleaved, period 5 = 1 special + 4 stream):
//   special: 272 outer-GEMM blocks (4 b-splits of 250) + 50 gwout   (322)
//   stream : 1024 gwin blocks + 256 gwrec blocks                    (1280)
#define N_OUTER 272
#define N_SPECIAL 322
#define N_GWIN 1024
#define N_STREAM 1280
#define MEGA_GRID 1610     // 322 periods of 5

__device__ __forceinline__ void do_outer(int oid, float* smem,
                                         float* __restrict__ gwin,
                                         float* __restrict__ gwrec) {
    // O[i,jj] = sum_b Lh[b,i] * C[b,jj],  C = [Faxn(784) | Fazn(256)]
    float (*As)[68] = (float(*)[68])smem;
    float (*Bs)[68] = (float(*)[68])(smem + 1088);
    const int split = oid / 68;            // 0..3, b-chunks of 250
    const int rem   = oid % 68;
    const int i0 = (rem & 3) * 64;
    const int j0 = (rem >> 2) * 64;
    const int kb0 = split * 250;
    const int kb1 = kb0 + 250;
    const int tid = threadIdx.x;
    const int tr = tid >> 4, tc = tid & 15;

    float acc[4][4];
#pragma unroll
    for (int i = 0; i < 4; i++)
#pragma unroll
        for (int j = 0; j < 4; j++) acc[i][j] = 0.f;

    for (int kb = kb0; kb < kb1; kb += 16) {
#pragma unroll
        for (int l = 0; l < 4; l++) {
            int idx = tid + l * 256;
            int kk = idx >> 6;
            int m  = idx & 63;       // consecutive lanes -> consecutive i/jj (coalesced)
            int k  = kb + kk;
            As[kk][m] = (k < kb1) ? g_Lh[k * NR + i0 + m] : 0.f;
            int jj = j0 + m;
            float bv = 0.f;
            if (k < kb1 && jj < 1040)
                bv = (jj < NI) ? g_Faxn[k * NI + jj] : g_Fazn[k * NR + (jj - NI)];
            Bs[kk][m] = bv;
        }
        __syncthreads();
#pragma unroll
        for (int kk = 0; kk < 16; kk++) {
            const float4 ra = *(const float4*)&As[kk][tr * 4];   // LDS.128
            const float4 rb = *(const float4*)&Bs[kk][tc * 4];   // LDS.128
            acc[0][0] = fmaf(ra.x, rb.x, acc[0][0]); acc[0][1] = fmaf(ra.x, rb.y, acc[0][1]);
            acc[0][2] = fmaf(ra.x, rb.z, acc[0][2]); acc[0][3] = fmaf(ra.x, rb.w, acc[0][3]);
            acc[1][0] = fmaf(ra.y, rb.x, acc[1][0]); acc[1][1] = fmaf(ra.y, rb.y, acc[1][1]);
            acc[1][2] = fmaf(ra.y, rb.z, acc[1][2]); acc[1][3] = fmaf(ra.y, rb.w, acc[1][3]);
            acc[2][0] = fmaf(ra.z, rb.x, acc[2][0]); acc[2][1] = fmaf(ra.z, rb.y, acc[2][1]);
            acc[2][2] = fmaf(ra.z, rb.z, acc[2][2]); acc[2][3] = fmaf(ra.z, rb.w, acc[2][3]);
            acc[3][0] = fmaf(ra.w, rb.x, acc[3][0]); acc[3][1] = fmaf(ra.w, rb.y, acc[3][1]);
            acc[3][2] = fmaf(ra.w, rb.z, acc[3][2]); acc[3][3] = fmaf(ra.w, rb.w, acc[3][3]);
        }
        __syncthreads();
    }
#pragma unroll
    for (int i = 0; i < 4; i++) {
        int row = i0 + tr * 4 + i;
#pragma unroll
        for (int j = 0; j < 4; j++) {
            int jj = j0 + tc * 4 + j;
            if (jj < NI)            atomicAdd(&gwin[row * NI + jj], acc[i][j]);
            else if (jj < NI + NR)  atomicAdd(&gwrec[row * NR + (jj - NI)], acc[i][j]);
        }
    }
}

__device__ __forceinline__ void do_gwout(int cid, float* smem, float* __restrict__ gwout) {
    float* s_err = smem;
    const int r = threadIdx.x;
    const int b0 = cid * 20;
    for (int t = r; t < 20 * NO; t += 256) s_err[t] = g_err[b0 * NO + t];
    __syncthreads();
    float acc[NO];
#pragma unroll
    for (int o = 0; o < NO; o++) acc[o] = 0.f;
    for (int bb = 0; bb < 20; bb++) {
        const float f = g_Fkzn[(b0 + bb) * NR + r];
#pragma unroll
        for (int o = 0; o < NO; o++) acc[o] = fmaf(s_err[bb * NO + o], f, acc[o]);
    }
#pragma unroll
    for (int o = 0; o < NO; o++) atomicAdd(&gwout[o * NR + r], acc[o]);
}

#define FMA4(A, C, F) \
    A.x = fmaf(C, F.x, A.x); A.y = fmaf(C, F.y, A.y); \
    A.z = fmaf(C, F.z, A.z); A.w = fmaf(C, F.w, A.w);

__device__ __forceinline__ void do_gwin(int sid, float* smem,
                                        const float* __restrict__ Fke_in,
                                        float* __restrict__ gwin) {
    float* s_kL = smem;
    const int t = threadIdx.x;
    const int i  = sid & 255;
    const int b0 = (sid >> 8) * 250;
    for (int tt = t; tt < 250; tt += 256) s_kL[tt] = g_kL[(b0 + tt) * NR + i];
    __syncthreads();
    if (t >= 196) return;

    const float4* fke = (const float4*)(Fke_in + ((size_t)b0 * NR + i) * NI) + t;
    const size_t stride = (size_t)NR * NI / 4;
    float4 a0 = make_float4(0.f, 0.f, 0.f, 0.f);
    float4 a1 = make_float4(0.f, 0.f, 0.f, 0.f);
    float4 a2 = make_float4(0.f, 0.f, 0.f, 0.f);
    float4 a3 = make_float4(0.f, 0.f, 0.f, 0.f);
#pragma unroll 1
    for (int bb = 0; bb < 248; bb += 4) {
        float4 f0 = __ldcs(fke + (size_t)(bb + 0) * stride);
        float4 f1 = __ldcs(fke + (size_t)(bb + 1) * stride);
        float4 f2 = __ldcs(fke + (size_t)(bb + 2) * stride);
        float4 f3 = __ldcs(fke + (size_t)(bb + 3) * stride);
        float c0 = s_kL[bb], c1 = s_kL[bb + 1], c2 = s_kL[bb + 2], c3 = s_kL[bb + 3];
        FMA4(a0, c0, f0) FMA4(a1, c1, f1) FMA4(a2, c2, f2) FMA4(a3, c3, f3)
    }
    {
        float4 f0 = __ldcs(fke + (size_t)248 * stride);
        float4 f1 = __ldcs(fke + (size_t)249 * stride);
        float c0 = s_kL[248], c1 = s_kL[249];
        FMA4(a0, c0, f0) FMA4(a1, c1, f1)
    }
    float* dst = gwin + i * NI + t * 4;
    atomicAdd(dst + 0, (a0.x + a1.x) + (a2.x + a3.x));
    atomicAdd(dst + 1, (a0.y + a1.y) + (a2.y + a3.y));
    atomicAdd(dst + 2, (a0.z + a1.z) + (a2.z + a3.z));
    atomicAdd(dst + 3, (a0.w + a1.w) + (a2.w + a3.w));
}

__device__ __forceinline__ void do_gwrec(int sid, float* smem,
                                         const float* __restrict__ Fke_rec,
                                         float* __restrict__ gwrec) {
    float* s_kL = smem;   // 1000 floats (4 rows x 250)
    const int t = threadIdx.x;
    const int i0 = (sid & 63) * 4;
    const int b0 = (sid >> 6) * 250;
    const int li = t >> 6;
    const int jv = t & 63;
    for (int tt = t; tt < 1000; tt += 256) {
        int lr = tt / 250, bb = tt % 250;
        s_kL[lr * 250 + bb] = g_kL[(b0 + bb) * NR + i0 + lr];
    }
    __syncthreads();

    const int i = i0 + li;
    const float4* fke = (const float4*)(Fke_rec + ((size_t)b0 * NR + i) * NR) + jv;
    const size_t stride = (size_t)NR * NR / 4;
    const float* kl = s_kL + li * 250;
    float4 a0 = make_float4(0.f, 0.f, 0.f, 0.f);
    float4 a1 = make_float4(0.f, 0.f, 0.f, 0.f);
    float4 a2 = make_float4(0.f, 0.f, 0.f, 0.f);
    float4 a3 = make_float4(0.f, 0.f, 0.f, 0.f);
#pragma unroll 1
    for (int bb = 0; bb < 248; bb += 4) {
        float4 f0 = __ldcs(fke + (size_t)(bb + 0) * stride);
        float4 f1 = __ldcs(fke + (size_t)(bb + 1) * stride);
        float4 f2 = __ldcs(fke + (size_t)(bb + 2) * stride);
        float4 f3 = __ldcs(fke + (size_t)(bb + 3) * stride);
        float c0 = kl[bb], c1 = kl[bb + 1], c2 = kl[bb + 2], c3 = kl[bb + 3];
        FMA4(a0, c0, f0) FMA4(a1, c1, f1) FMA4(a2, c2, f2) FMA4(a3, c3, f3)
    }
    {
        float4 f0 = __ldcs(fke + (size_t)248 * stride);
        float4 f1 = __ldcs(fke + (size_t)249 * stride);
        float c0 = kl[248], c1 = kl[249];
        FMA4(a0, c0, f0) FMA4(a1, c1, f1)
    }
    float* dst = gwrec + i * NR + jv * 4;
    atomicAdd(dst + 0, (a0.x + a1.x) + (a2.x + a3.x));
    atomicAdd(dst + 1, (a0.y + a1.y) + (a2.y + a3.y));
    atomicAdd(dst + 2, (a0.z + a1.z) + (a2.z + a3.z));
    atomicAdd(dst + 3, (a0.w + a1.w) + (a2.w + a3.w));
}

__global__ void __launch_bounds__(256)
k_mega(const float* __restrict__ Fke_in, const float* __restrict__ Fke_rec,
       float* __restrict__ gwin, float* __restrict__ gwrec, float* __restrict__ gwout) {
    __shared__ __align__(16) float smem[2176];
    const int p = blockIdx.x / 5;
    const int l = blockIdx.x % 5;
    if (l == 0) {
        int sid = p;
        if (sid >= N_SPECIAL) return;
        if (sid < N_OUTER) do_outer(sid, smem, gwin, gwrec);
        else               do_gwout(sid - N_OUTER, smem, gwout);
    } else {
        int sid = p * 4 + (l - 1);
        if (sid >= N_STREAM) return;
        if (sid < N_GWIN) do_gwin(sid, smem, Fke_in, gwin);
        else              do_gwrec(sid - N_GWIN, smem, Fke_rec, gwrec);
    }
}

// ---------------- launch ----------------
extern "C" void kernel_launch(void* const* d_in, const int* in_sizes, int n_in,
                              void* d_out, int out_size) {
    const float* x       = (const float*)d_in[0];
    const float* yt      = (const float*)d_in[2];
    const float* w_in    = (const float*)d_in[3];
    const float* w_rec   = (const float*)d_in[4];
    const float* w_out   = (const float*)d_in[5];
    const float* v       = (const float*)d_in[6];
    const float* vo      = (const float*)d_in[7];
    const float* z       = (const float*)d_in[8];
    const float* Faz     = (const float*)d_in[9];
    const float* Fkz     = (const float*)d_in[10];
    const float* Fax     = (const float*)d_in[11];
    const float* Fke_rec = (const float*)d_in[12];
    const float* Fke_in  = (const float*)d_in[13];

    float* out     = (float*)d_out;
    float* yo_o    = out;
    float* gwin_o  = out + NB * NO;
    float* gwrec_o = gwin_o + NR * NI;
    float* gwout_o = gwrec_o + NR * NR;

    k_prep<<<PREP_GRID, 256>>>(x, z, w_in, w_rec, Fax, Faz, gwin_o, gwrec_o, gwout_o);
    k_step<<<NB, NR>>>(v, vo, z, Fkz, w_out, yt, yo_o);
    k_mega<<<MEGA_GRID, 256>>>(Fke_in, Fke_rec, gwin_o, gwrec_o, gwout_o);
}

// round 12
// speedup vs baseline: 1.0623x; 1.0283x over previous
#include <cuda_runtime.h>

// Problem dims
#define NB 1000
#define NI 784
#define NR 256
#define NO 10

#define ALPHA 0.8f
#define KAPPA 0.8f

#define NSPLIT 17          // gemm split-K count (chunks of 64 over K=1040; last=16)

// ---------------- scratch (__device__ globals; no allocation) ----------------
__device__ float g_vpre_p[NSPLIT * NB * NR];  // split-K partials (no atomics)
__device__ float g_kL  [NB * NR];
__device__ float g_Lh  [NB * NR];
__device__ float g_Fazn[NB * NR];
__device__ float g_Fkzn[NB * NR];
__device__ float g_Faxn[NB * NI];
__device__ float g_err [NB * NO];

// ================= PREP KERNEL =================
// blocks [0,544): vpre split-K GEMM, 128x64 tiles, 8x4 micro, DOUBLE-BUFFERED smem
// blocks [544,608): aux — zero gw outputs + Faxn + Fazn (input-only, runs in GEMM's shadow)
#define N_GEMM 544
#define PREP_GRID 608

__global__ void __launch_bounds__(256)
k_prep(const float* __restrict__ x, const float* __restrict__ z,
       const float* __restrict__ w_in, const float* __restrict__ w_rec,
       const float* __restrict__ Fax, const float* __restrict__ Faz,
       float* __restrict__ gwin, float* __restrict__ gwrec, float* __restrict__ gwout) {
    if (blockIdx.x >= N_GEMM) {
        // ---- aux role ----
        int idx = (blockIdx.x - N_GEMM) * 256 + threadIdx.x;
        const int stride = (PREP_GRID - N_GEMM) * 256;   // 16384
        const float4 zz = make_float4(0.f, 0.f, 0.f, 0.f);
        for (int i = idx; i < NR * NI / 4; i += stride) ((float4*)gwin)[i] = zz;
        for (int i = idx; i < NR * NR / 4; i += stride) ((float4*)gwrec)[i] = zz;
        for (int i = idx; i < NO * NR / 4; i += stride) ((float4*)gwout)[i] = zz;
        // Faxn = ALPHA*Fax + x
        for (int i = idx; i < NB * NI / 4; i += stride) {
            float4 f = ((const float4*)Fax)[i];
            float4 xx = ((const float4*)x)[i];
            float4 o;
            o.x = fmaf(ALPHA, f.x, xx.x); o.y = fmaf(ALPHA, f.y, xx.y);
            o.z = fmaf(ALPHA, f.z, xx.z); o.w = fmaf(ALPHA, f.w, xx.w);
            ((float4*)g_Faxn)[i] = o;
        }
        // Fazn = ALPHA*Faz + z (old z)
        for (int i = idx; i < NB * NR / 4; i += stride) {
            float4 f = ((const float4*)Faz)[i];
            float4 zo = ((const float4*)z)[i];
            float4 o;
            o.x = fmaf(ALPHA, f.x, zo.x); o.y = fmaf(ALPHA, f.y, zo.y);
            o.z = fmaf(ALPHA, f.z, zo.z); o.w = fmaf(ALPHA, f.w, zo.w);
            ((float4*)g_Fazn)[i] = o;
        }
        return;
    }
    // ---- GEMM role: vpre_p[s][b,r] = sum_{k in chunk s} A[b,k] * W[r,k] ----
    __shared__ __align__(16) float As[2][16][136];
    __shared__ __align__(16) float Ws[2][16][72];
    const int bi = blockIdx.x;
    const int split = bi >> 5;            // 0..16
    const int rem   = bi & 31;
    const int row0 = (rem & 7) * 128;     // batch tile
    const int col0 = (rem >> 3) * 64;     // rec-unit tile
    const int tid = threadIdx.x;
    const int tr = tid >> 4, tc = tid & 15;
    const int kk_l = tid & 15;
    const int m_l  = tid >> 4;

    const int k_begin = split * 64;
    const int k_end   = (k_begin + 64 < 1040) ? (k_begin + 64) : 1040;

    float avp[8], wvp[4];
    {
        const int k = k_begin + kk_l;
#pragma unroll
        for (int l = 0; l < 8; l++) {
            int b = row0 + m_l + l * 16;
            float av = 0.f;
            if (b < NB) av = (k < NI) ? x[b * NI + k] : z[b * NR + (k - NI)];
            avp[l] = av;
        }
#pragma unroll
        for (int l = 0; l < 4; l++) {
            int r = col0 + m_l + l * 16;
            if (k < NI) wvp[l] = w_in[r * NI + k];
            else { int kr = k - NI; wvp[l] = (kr == r) ? 0.f : w_rec[r * NR + kr]; }
        }
#pragma unroll
        for (int l = 0; l < 8; l++) As[0][kk_l][m_l + l * 16] = avp[l];
#pragma unroll
        for (int l = 0; l < 4; l++) Ws[0][kk_l][m_l + l * 16] = wvp[l];
    }
    __syncthreads();

    float acc[8][4];
#pragma unroll
    for (int i = 0; i < 8; i++)
#pragma unroll
        for (int j = 0; j < 4; j++) acc[i][j] = 0.f;

    int buf = 0;
    for (int kb = k_begin; kb < k_end; kb += 16) {
        const bool has_next = (kb + 16) < k_end;
        if (has_next) {
            const int k = kb + 16 + kk_l;
#pragma unroll
            for (int l = 0; l < 8; l++) {
                int b = row0 + m_l + l * 16;
                float av = 0.f;
                if (b < NB) av = (k < NI) ? x[b * NI + k] : z[b * NR + (k - NI)];
                avp[l] = av;
            }
#pragma unroll
            for (int l = 0; l < 4; l++) {
                int r = col0 + m_l + l * 16;
                if (k < NI) wvp[l] = w_in[r * NI + k];
                else { int kr = k - NI; wvp[l] = (kr == r) ? 0.f : w_rec[r * NR + kr]; }
            }
        }
#pragma unroll
        for (int kk = 0; kk < 16; kk++) {
            const float4 ra0 = *(const float4*)&As[buf][kk][tr * 8];
            const float4 ra1 = *(const float4*)&As[buf][kk][tr * 8 + 4];
            const float4 rb  = *(const float4*)&Ws[buf][kk][tc * 4];
            const float ra[8] = {ra0.x, ra0.y, ra0.z, ra0.w, ra1.x, ra1.y, ra1.z, ra1.w};
#pragma unroll
            for (int i = 0; i < 8; i++) {
                acc[i][0] = fmaf(ra[i], rb.x, acc[i][0]);
                acc[i][1] = fmaf(ra[i], rb.y, acc[i][1]);
                acc[i][2] = fmaf(ra[i], rb.z, acc[i][2]);
                acc[i][3] = fmaf(ra[i], rb.w, acc[i][3]);
            }
        }
        if (has_next) {
            const int nb = buf ^ 1;
#pragma unroll
            for (int l = 0; l < 8; l++) As[nb][kk_l][m_l + l * 16] = avp[l];
#pragma unroll
            for (int l = 0; l < 4; l++) Ws[nb][kk_l][m_l + l * 16] = wvp[l];
            __syncthreads();
            buf = nb;
        }
    }
    float* dst = g_vpre_p + (size_t)split * NB * NR;
#pragma unroll
    for (int i = 0; i < 8; i++) {
        int b = row0 + tr * 8 + i;
        if (b < NB) {
            float4 vv = make_float4(acc[i][0], acc[i][1], acc[i][2], acc[i][3]);
            *(float4*)(dst + b * NR + col0 + tc * 4) = vv;
        }
    }
}

// ---------------- per-batch fused step (Faxn/Fazn handled by prep aux) ----------------
__global__ void __launch_bounds__(256)
k_step(const float* __restrict__ v, const float* __restrict__ vo,
       const float* __restrict__ z, const float* __restrict__ Fkz,
       const float* __restrict__ w_out, const float* __restrict__ yt,
       float* __restrict__ yo_out) {
    const int b = blockIdx.x;
    const int r = threadIdx.x;
    __shared__ float s_zn[NR];
    __shared__ float s_err[NO];

    const int ir = b * NR + r;
    float vpre = 0.f;
#pragma unroll
    for (int s = 0; s < NSPLIT; s++) vpre += g_vpre_p[(size_t)s * NB * NR + ir];

    const float zb = z[ir];
    const float vn = vpre + ALPHA * v[ir] * (1.f - zb);
    const float zn = (vn > 1.f) ? 1.f : 0.f;
    s_zn[r] = zn;
    const float h = fmaxf(0.f, 1.f - fabsf(vn - 1.f));
    g_Fkzn[ir] = KAPPA * Fkz[ir] + zn;
    __syncthreads();

    if (r < 32) {
        const int lane = r;
        float part[NO];
#pragma unroll
        for (int o = 0; o < NO; o++) {
            float p = 0.f;
#pragma unroll
            for (int k = 0; k < 8; k++)
                p = fmaf(s_zn[lane + 32 * k], w_out[o * NR + lane + 32 * k], p);
#pragma unroll
            for (int off = 16; off; off >>= 1) p += __shfl_xor_sync(0xffffffffu, p, off);
            part[o] = p;
        }
        if (lane == 0) {
            float vn_o[NO];
            float m = -1e30f;
#pragma unroll
            for (int o = 0; o < NO; o++) {
                vn_o[o] = KAPPA * vo[b * NO + o] + part[o];
                m = fmaxf(m, vn_o[o]);
            }
            float e[NO], s = 0.f;
#pragma unroll
            for (int o = 0; o < NO; o++) { e[o] = expf(vn_o[o] - m); s += e[o]; }
            const float inv = 1.f / s;
#pragma unroll
            for (int o = 0; o < NO; o++) {
                const float yo = e[o] * inv;
                yo_out[b * NO + o] = yo;
                const float er = yo - yt[b * NO + o];
                s_err[o] = er;
                g_err[b * NO + o] = er;
            }
        }
    }
    __syncthreads();

    float L = 0.f;
#pragma unroll
    for (int o = 0; o < NO; o++) L = fmaf(s_err[o], w_out[o * NR + r], L);
    g_kL[ir] = KAPPA * L;
    g_Lh[ir] = L * h;
}

// ================= MEGA KERNEL =================
// Finer stream granularity: b split 8 ways (125 per chunk) to halve wave-tail loss.
// Roles (interleaved, period 9 = 1 special + 8 stream):
//   special: 272 outer-GEMM blocks (4 b-splits of 250) + 50 gwout   (322)
//   stream : 2048 gwin blocks + 512 gwrec blocks                    (2560)
#define N_OUTER 272
#define N_SPECIAL 322
#define N_GWIN 2048
#define N_STREAM 2560
#define MEGA_GRID 2898     // 322 periods of 9

__device__ __forceinline__ void do_outer(int oid, float* smem,
                                         float* __restrict__ gwin,
                                         float* __restrict__ gwrec) {
    // O[i,jj] = sum_b Lh[b,i] * C[b,jj],  C = [Faxn(784) | Fazn(256)]
    float (*As)[68] = (float(*)[68])smem;
    float (*Bs)[68] = (float(*)[68])(smem + 1088);
    const int split = oid / 68;            // 0..3, b-chunks of 250
    const int rem   = oid % 68;
    const int i0 = (rem & 3) * 64;
    const int j0 = (rem >> 2) * 64;
    const int kb0 = split * 250;
    const int kb1 = kb0 + 250;
    const int tid = threadIdx.x;
    const int tr = tid >> 4, tc = tid & 15;

    float acc[4][4];
#pragma unroll
    for (int i = 0; i < 4; i++)
#pragma unroll
        for (int j = 0; j < 4; j++) acc[i][j] = 0.f;

    for (int kb = kb0; kb < kb1; kb += 16) {
#pragma unroll
        for (int l = 0; l < 4; l++) {
            int idx = tid + l * 256;
            int kk = idx >> 6;
            int m  = idx & 63;
            int k  = kb + kk;
            As[kk][m] = (k < kb1) ? g_Lh[k * NR + i0 + m] : 0.f;
            int jj = j0 + m;
            float bv = 0.f;
            if (k < kb1 && jj < 1040)
                bv = (jj < NI) ? g_Faxn[k * NI + jj] : g_Fazn[k * NR + (jj - NI)];
            Bs[kk][m] = bv;
        }
        __syncthreads();
#pragma unroll
        for (int kk = 0; kk < 16; kk++) {
            const float4 ra = *(const float4*)&As[kk][tr * 4];
            const float4 rb = *(const float4*)&Bs[kk][tc * 4];
            acc[0][0] = fmaf(ra.x, rb.x, acc[0][0]); acc[0][1] = fmaf(ra.x, rb.y, acc[0][1]);
            acc[0][2] = fmaf(ra.x, rb.z, acc[0][2]); acc[0][3] = fmaf(ra.x, rb.w, acc[0][3]);
            acc[1][0] = fmaf(ra.y, rb.x, acc[1][0]); acc[1][1] = fmaf(ra.y, rb.y, acc[1][1]);
            acc[1][2] = fmaf(ra.y, rb.z, acc[1][2]); acc[1][3] = fmaf(ra.y, rb.w, acc[1][3]);
            acc[2][0] = fmaf(ra.z, rb.x, acc[2][0]); acc[2][1] = fmaf(ra.z, rb.y, acc[2][1]);
            acc[2][2] = fmaf(ra.z, rb.z, acc[2][2]); acc[2][3] = fmaf(ra.z, rb.w, acc[2][3]);
            acc[3][0] = fmaf(ra.w, rb.x, acc[3][0]); acc[3][1] = fmaf(ra.w, rb.y, acc[3][1]);
            acc[3][2] = fmaf(ra.w, rb.z, acc[3][2]); acc[3][3] = fmaf(ra.w, rb.w, acc[3][3]);
        }
        __syncthreads();
    }
#pragma unroll
    for (int i = 0; i < 4; i++) {
        int row = i0 + tr * 4 + i;
#pragma unroll
        for (int j = 0; j < 4; j++) {
            int jj = j0 + tc * 4 + j;
            if (jj < NI)            atomicAdd(&gwin[row * NI + jj], acc[i][j]);
            else if (jj < NI + NR)  atomicAdd(&gwrec[row * NR + (jj - NI)], acc[i][j]);
        }
    }
}

__device__ __forceinline__ void do_gwout(int cid, float* smem, float* __restrict__ gwout) {
    float* s_err = smem;
    const int r = threadIdx.x;
    const int b0 = cid * 20;
    for (int t = r; t < 20 * NO; t += 256) s_err[t] = g_err[b0 * NO + t];
    __syncthreads();
    float acc[NO];
#pragma unroll
    for (int o = 0; o < NO; o++) acc[o] = 0.f;
    for (int bb = 0; bb < 20; bb++) {
        const float f = g_Fkzn[(b0 + bb) * NR + r];
#pragma unroll
        for (int o = 0; o < NO; o++) acc[o] = fmaf(s_err[bb * NO + o], f, acc[o]);
    }
#pragma unroll
    for (int o = 0; o < NO; o++) atomicAdd(&gwout[o * NR + r], acc[o]);
}

#define FMA4(A, C, F) \
    A.x = fmaf(C, F.x, A.x); A.y = fmaf(C, F.y, A.y); \
    A.z = fmaf(C, F.z, A.z); A.w = fmaf(C, F.w, A.w);

// 125 batches per stream block (8 chunks)
__device__ __forceinline__ void do_gwin(int sid, float* smem,
                                        const float* __restrict__ Fke_in,
                                        float* __restrict__ gwin) {
    float* s_kL = smem;
    const int t = threadIdx.x;
    const int i  = sid & 255;
    const int b0 = (sid >> 8) * 125;     // chunk 0..7
    if (t < 125) s_kL[t] = g_kL[(b0 + t) * NR + i];
    __syncthreads();
    if (t >= 196) return;

    const float4* fke = (const float4*)(Fke_in + ((size_t)b0 * NR + i) * NI) + t;
    const size_t stride = (size_t)NR * NI / 4;
    float4 a0 = make_float4(0.f, 0.f, 0.f, 0.f);
    float4 a1 = make_float4(0.f, 0.f, 0.f, 0.f);
    float4 a2 = make_float4(0.f, 0.f, 0.f, 0.f);
    float4 a3 = make_float4(0.f, 0.f, 0.f, 0.f);
#pragma unroll 1
    for (int bb = 0; bb < 124; bb += 4) {
        float4 f0 = __ldcs(fke + (size_t)(bb + 0) * stride);
        float4 f1 = __ldcs(fke + (size_t)(bb + 1) * stride);
        float4 f2 = __ldcs(fke + (size_t)(bb + 2) * stride);
        float4 f3 = __ldcs(fke + (size_t)(bb + 3) * stride);
        float c0 = s_kL[bb], c1 = s_kL[bb + 1], c2 = s_kL[bb + 2], c3 = s_kL[bb + 3];
        FMA4(a0, c0, f0) FMA4(a1, c1, f1) FMA4(a2, c2, f2) FMA4(a3, c3, f3)
    }
    {
        float4 f0 = __ldcs(fke + (size_t)124 * stride);
        float c0 = s_kL[124];
        FMA4(a0, c0, f0)
    }
    float* dst = gwin + i * NI + t * 4;
    atomicAdd(dst + 0, (a0.x + a1.x) + (a2.x + a3.x));
    atomicAdd(dst + 1, (a0.y + a1.y) + (a2.y + a3.y));
    atomicAdd(dst + 2, (a0.z + a1.z) + (a2.z + a3.z));
    atomicAdd(dst + 3, (a0.w + a1.w) + (a2.w + a3.w));
}

__device__ __forceinline__ void do_gwrec(int sid, float* smem,
                                         const float* __restrict__ Fke_rec,
                                         float* __restrict__ gwrec) {
    float* s_kL = smem;   // 500 floats (4 rows x 125)
    const int t = threadIdx.x;
    const int i0 = (sid & 63) * 4;
    const int b0 = (sid >> 6) * 125;     // chunk 0..7
    const int li = t >> 6;
    const int jv = t & 63;
    for (int tt = t; tt < 500; tt += 256) {
        int lr = tt / 125, bb = tt % 125;
        s_kL[lr * 125 + bb] = g_kL[(b0 + bb) * NR + i0 + lr];
    }
    __syncthreads();

    const int i = i0 + li;
    const float4* fke = (const float4*)(Fke_rec + ((size_t)b0 * NR + i) * NR) + jv;
    const size_t stride = (size_t)NR * NR / 4;
    const float* kl = s_kL + li * 125;
    float4 a0 = make_float4(0.f, 0.f, 0.f, 0.f);
    float4 a1 = make_float4(0.f, 0.f, 0.f, 0.f);
    float4 a2 = make_float4(0.f, 0.f, 0.f, 0.f);
    float4 a3 = make_float4(0.f, 0.f, 0.f, 0.f);
#pragma unroll 1
    for (int bb = 0; bb < 124; bb += 4) {
        float4 f0 = __ldcs(fke + (size_t)(bb + 0) * stride);
        float4 f1 = __ldcs(fke + (size_t)(bb + 1) * stride);
        float4 f2 = __ldcs(fke + (size_t)(bb + 2) * stride);
        float4 f3 = __ldcs(fke + (size_t)(bb + 3) * stride);
        float c0 = kl[bb], c1 = kl[bb + 1], c2 = kl[bb + 2], c3 = kl[bb + 3];
        FMA4(a0, c0, f0) FMA4(a1, c1, f1) FMA4(a2, c2, f2) FMA4(a3, c3, f3)
    }
    {
        float4 f0 = __ldcs(fke + (size_t)124 * stride);
        float c0 = kl[124];
        FMA4(a0, c0, f0)
    }
    float* dst = gwrec + i * NR + jv * 4;
    atomicAdd(dst + 0, (a0.x + a1.x) + (a2.x + a3.x));
    atomicAdd(dst + 1, (a0.y + a1.y) + (a2.y + a3.y));
    atomicAdd(dst + 2, (a0.z + a1.z) + (a2.z + a3.z));
    atomicAdd(dst + 3, (a0.w + a1.w) + (a2.w + a3.w));
}

__global__ void __launch_bounds__(256)
k_mega(const float* __restrict__ Fke_in, const float* __restrict__ Fke_rec,
       float* __restrict__ gwin, float* __restrict__ gwrec, float* __restrict__ gwout) {
    __shared__ __align__(16) float smem[2176];
    const int p = blockIdx.x / 9;
    const int l = blockIdx.x % 9;
    if (l == 0) {
        int sid = p;
        if (sid >= N_SPECIAL) return;
        if (sid < N_OUTER) do_outer(sid, smem, gwin, gwrec);
        else               do_gwout(sid - N_OUTER, smem, gwout);
    } else {
        int sid = p * 8 + (l - 1);
        if (sid >= N_STREAM) return;
        if (sid < N_GWIN) do_gwin(sid, smem, Fke_in, gwin);
        else              do_gwrec(sid - N_GWIN, smem, Fke_rec, gwrec);
    }
}

// ---------------- launch ----------------
extern "C" void kernel_launch(void* const* d_in, const int* in_sizes, int n_in,
                              void* d_out, int out_size) {
    const float* x       = (const float*)d_in[0];
    const float* yt      = (const float*)d_in[2];
    const float* w_in    = (const float*)d_in[3];
    const float* w_rec   = (const float*)d_in[4];
    const float* w_out   = (const float*)d_in[5];
    const float* v       = (const float*)d_in[6];
    const float* vo      = (const float*)d_in[7];
    const float* z       = (const float*)d_in[8];
    const float* Faz     = (const float*)d_in[9];
    const float* Fkz     = (const float*)d_in[10];
    const float* Fax     = (const float*)d_in[11];
    const float* Fke_rec = (const float*)d_in[12];
    const float* Fke_in  = (const float*)d_in[13];

    float* out     = (float*)d_out;
    float* yo_o    = out;
    float* gwin_o  = out + NB * NO;
    float* gwrec_o = gwin_o + NR * NI;
    float* gwout_o = gwrec_o + NR * NR;

    k_prep<<<PREP_GRID, 256>>>(x, z, w_in, w_rec, Fax, Faz, gwin_o, gwrec_o, gwout_o);
    k_step<<<NB, NR>>>(v, vo, z, Fkz, w_out, yt, yo_o);
    k_mega<<<MEGA_GRID, 256>>>(Fke_in, Fke_rec, gwin_o, gwrec_o, gwout_o);
}

// round 13
// speedup vs baseline: 1.0751x; 1.0121x over previous
#include <cuda_runtime.h>

// Problem dims
#define NB 1000
#define NI 784
#define NR 256
#define NO 10

#define ALPHA 0.8f
#define KAPPA 0.8f

#define NSPLIT 17          // gemm split-K count (chunks of 64 over K=1040; last=16)

// ---------------- scratch (__device__ globals; no allocation) ----------------
__device__ float g_vpre_p[NSPLIT * NB * NR];  // split-K partials (no atomics)
__device__ float g_kL  [NB * NR];
__device__ float g_Lh  [NB * NR];
__device__ float g_Fazn[NB * NR];
__device__ float g_Fkzn[NB * NR];
__device__ float g_Faxn[NB * NI];
__device__ float g_err [NB * NO];

// ================= PREP KERNEL =================
// blocks [0,544): vpre split-K GEMM, 128x64 tiles, 8x4 micro, double-buffered smem
// blocks [544,608): aux — zero gw outputs + Faxn + Fazn
#define N_GEMM 544
#define PREP_GRID 608

__global__ void __launch_bounds__(256)
k_prep(const float* __restrict__ x, const float* __restrict__ z,
       const float* __restrict__ w_in, const float* __restrict__ w_rec,
       const float* __restrict__ Fax, const float* __restrict__ Faz,
       float* __restrict__ gwin, float* __restrict__ gwrec, float* __restrict__ gwout) {
#if __CUDA_ARCH__ >= 900
    cudaTriggerProgrammaticLaunchCompletion();   // let k_step's blocks schedule early
#endif
    if (blockIdx.x >= N_GEMM) {
        // ---- aux role ----
        int idx = (blockIdx.x - N_GEMM) * 256 + threadIdx.x;
        const int stride = (PREP_GRID - N_GEMM) * 256;   // 16384
        const float4 zz = make_float4(0.f, 0.f, 0.f, 0.f);
        for (int i = idx; i < NR * NI / 4; i += stride) ((float4*)gwin)[i] = zz;
        for (int i = idx; i < NR * NR / 4; i += stride) ((float4*)gwrec)[i] = zz;
        for (int i = idx; i < NO * NR / 4; i += stride) ((float4*)gwout)[i] = zz;
        for (int i = idx; i < NB * NI / 4; i += stride) {
            float4 f = ((const float4*)Fax)[i];
            float4 xx = ((const float4*)x)[i];
            float4 o;
            o.x = fmaf(ALPHA, f.x, xx.x); o.y = fmaf(ALPHA, f.y, xx.y);
            o.z = fmaf(ALPHA, f.z, xx.z); o.w = fmaf(ALPHA, f.w, xx.w);
            ((float4*)g_Faxn)[i] = o;
        }
        for (int i = idx; i < NB * NR / 4; i += stride) {
            float4 f = ((const float4*)Faz)[i];
            float4 zo = ((const float4*)z)[i];
            float4 o;
            o.x = fmaf(ALPHA, f.x, zo.x); o.y = fmaf(ALPHA, f.y, zo.y);
            o.z = fmaf(ALPHA, f.z, zo.z); o.w = fmaf(ALPHA, f.w, zo.w);
            ((float4*)g_Fazn)[i] = o;
        }
        return;
    }
    // ---- GEMM role ----
    __shared__ __align__(16) float As[2][16][136];
    __shared__ __align__(16) float Ws[2][16][72];
    const int bi = blockIdx.x;
    const int split = bi >> 5;
    const int rem   = bi & 31;
    const int row0 = (rem & 7) * 128;
    const int col0 = (rem >> 3) * 64;
    const int tid = threadIdx.x;
    const int tr = tid >> 4, tc = tid & 15;
    const int kk_l = tid & 15;
    const int m_l  = tid >> 4;

    const int k_begin = split * 64;
    const int k_end   = (k_begin + 64 < 1040) ? (k_begin + 64) : 1040;

    float avp[8], wvp[4];
    {
        const int k = k_begin + kk_l;
#pragma unroll
        for (int l = 0; l < 8; l++) {
            int b = row0 + m_l + l * 16;
            float av = 0.f;
            if (b < NB) av = (k < NI) ? x[b * NI + k] : z[b * NR + (k - NI)];
            avp[l] = av;
        }
#pragma unroll
        for (int l = 0; l < 4; l++) {
            int r = col0 + m_l + l * 16;
            if (k < NI) wvp[l] = w_in[r * NI + k];
            else { int kr = k - NI; wvp[l] = (kr == r) ? 0.f : w_rec[r * NR + kr]; }
        }
#pragma unroll
        for (int l = 0; l < 8; l++) As[0][kk_l][m_l + l * 16] = avp[l];
#pragma unroll
        for (int l = 0; l < 4; l++) Ws[0][kk_l][m_l + l * 16] = wvp[l];
    }
    __syncthreads();

    float acc[8][4];
#pragma unroll
    for (int i = 0; i < 8; i++)
#pragma unroll
        for (int j = 0; j < 4; j++) acc[i][j] = 0.f;

    int buf = 0;
    for (int kb = k_begin; kb < k_end; kb += 16) {
        const bool has_next = (kb + 16) < k_end;
        if (has_next) {
            const int k = kb + 16 + kk_l;
#pragma unroll
            for (int l = 0; l < 8; l++) {
                int b = row0 + m_l + l * 16;
                float av = 0.f;
                if (b < NB) av = (k < NI) ? x[b * NI + k] : z[b * NR + (k - NI)];
                avp[l] = av;
            }
#pragma unroll
            for (int l = 0; l < 4; l++) {
                int r = col0 + m_l + l * 16;
                if (k < NI) wvp[l] = w_in[r * NI + k];
                else { int kr = k - NI; wvp[l] = (kr == r) ? 0.f : w_rec[r * NR + kr]; }
            }
        }
#pragma unroll
        for (int kk = 0; kk < 16; kk++) {
            const float4 ra0 = *(const float4*)&As[buf][kk][tr * 8];
            const float4 ra1 = *(const float4*)&As[buf][kk][tr * 8 + 4];
            const float4 rb  = *(const float4*)&Ws[buf][kk][tc * 4];
            const float ra[8] = {ra0.x, ra0.y, ra0.z, ra0.w, ra1.x, ra1.y, ra1.z, ra1.w};
#pragma unroll
            for (int i = 0; i < 8; i++) {
                acc[i][0] = fmaf(ra[i], rb.x, acc[i][0]);
                acc[i][1] = fmaf(ra[i], rb.y, acc[i][1]);
                acc[i][2] = fmaf(ra[i], rb.z, acc[i][2]);
                acc[i][3] = fmaf(ra[i], rb.w, acc[i][3]);
            }
        }
        if (has_next) {
            const int nb = buf ^ 1;
#pragma unroll
            for (int l = 0; l < 8; l++) As[nb][kk_l][m_l + l * 16] = avp[l];
#pragma unroll
            for (int l = 0; l < 4; l++) Ws[nb][kk_l][m_l + l * 16] = wvp[l];
            __syncthreads();
            buf = nb;
        }
    }
    float* dst = g_vpre_p + (size_t)split * NB * NR;
#pragma unroll
    for (int i = 0; i < 8; i++) {
        int b = row0 + tr * 8 + i;
        if (b < NB) {
            float4 vv = make_float4(acc[i][0], acc[i][1], acc[i][2], acc[i][3]);
            *(float4*)(dst + b * NR + col0 + tc * 4) = vv;
        }
    }
}

// ---------------- per-batch fused step ----------------
__global__ void __launch_bounds__(256)
k_step(const float* __restrict__ v, const float* __restrict__ vo,
       const float* __restrict__ z, const float* __restrict__ Fkz,
       const float* __restrict__ w_out, const float* __restrict__ yt,
       float* __restrict__ yo_out) {
    const int b = blockIdx.x;
    const int r = threadIdx.x;
    __shared__ float s_zn[NR];
    __shared__ float s_err[NO];

    const int ir = b * NR + r;
#if __CUDA_ARCH__ >= 900
    cudaTriggerProgrammaticLaunchCompletion();   // let k_mega's blocks schedule early
#endif
    // pre-sync: inputs only
    const float zb = z[ir];
    const float fkzv = Fkz[ir];
    const float vv = v[ir];
#if __CUDA_ARCH__ >= 900
    cudaGridDependencySynchronize();             // wait for k_prep's vpre partials
#endif
    float vpre = 0.f;
#pragma unroll
    for (int s = 0; s < NSPLIT; s++) vpre += g_vpre_p[(size_t)s * NB * NR + ir];

    const float vn = vpre + ALPHA * vv * (1.f - zb);
    const float zn = (vn > 1.f) ? 1.f : 0.f;
    s_zn[r] = zn;
    const float h = fmaxf(0.f, 1.f - fabsf(vn - 1.f));
    g_Fkzn[ir] = KAPPA * fkzv + zn;
    __syncthreads();

    if (r < 32) {
        const int lane = r;
        float part[NO];
#pragma unroll
        for (int o = 0; o < NO; o++) {
            float p = 0.f;
#pragma unroll
            for (int k = 0; k < 8; k++)
                p = fmaf(s_zn[lane + 32 * k], w_out[o * NR + lane + 32 * k], p);
#pragma unroll
            for (int off = 16; off; off >>= 1) p += __shfl_xor_sync(0xffffffffu, p, off);
            part[o] = p;
        }
        if (lane == 0) {
            float vn_o[NO];
            float m = -1e30f;
#pragma unroll
            for (int o = 0; o < NO; o++) {
                vn_o[o] = KAPPA * vo[b * NO + o] + part[o];
                m = fmaxf(m, vn_o[o]);
            }
            float e[NO], s = 0.f;
#pragma unroll
            for (int o = 0; o < NO; o++) { e[o] = expf(vn_o[o] - m); s += e[o]; }
            const float inv = 1.f / s;
#pragma unroll
            for (int o = 0; o < NO; o++) {
                const float yo = e[o] * inv;
                yo_out[b * NO + o] = yo;
                const float er = yo - yt[b * NO + o];
                s_err[o] = er;
                g_err[b * NO + o] = er;
            }
        }
    }
    __syncthreads();

    float L = 0.f;
#pragma unroll
    for (int o = 0; o < NO; o++) L = fmaf(s_err[o], w_out[o * NR + r], L);
    g_kL[ir] = KAPPA * L;
    g_Lh[ir] = L * h;
}

// ================= MEGA KERNEL =================
// Roles (interleaved, period 9 = 1 special + 8 stream):
//   special: 272 outer-GEMM blocks (4 b-splits of 250) + 50 gwout   (322)
//   stream : 2048 gwin blocks + 512 gwrec blocks (b chunks of 125)  (2560)
#define N_OUTER 272
#define N_SPECIAL 322
#define N_GWIN 2048
#define N_STREAM 2560
#define MEGA_GRID 2898     // 322 periods of 9

__device__ __forceinline__ void grid_dep_sync() {
#if __CUDA_ARCH__ >= 900
    cudaGridDependencySynchronize();
#endif
}

__device__ __forceinline__ void do_outer(int oid, float* smem,
                                         float* __restrict__ gwin,
                                         float* __restrict__ gwrec) {
    grid_dep_sync();   // needs g_Lh (step) + g_Faxn/g_Fazn (prep)
    // O[i,jj] = sum_b Lh[b,i] * C[b,jj],  C = [Faxn(784) | Fazn(256)]
    float (*As)[68] = (float(*)[68])smem;
    float (*Bs)[68] = (float(*)[68])(smem + 1088);
    const int split = oid / 68;            // 0..3, b-chunks of 250
    const int rem   = oid % 68;
    const int i0 = (rem & 3) * 64;
    const int j0 = (rem >> 2) * 64;
    const int kb0 = split * 250;
    const int kb1 = kb0 + 250;
    const int tid = threadIdx.x;
    const int tr = tid >> 4, tc = tid & 15;

    float acc[4][4];
#pragma unroll
    for (int i = 0; i < 4; i++)
#pragma unroll
        for (int j = 0; j < 4; j++) acc[i][j] = 0.f;

    for (int kb = kb0; kb < kb1; kb += 16) {
#pragma unroll
        for (int l = 0; l < 4; l++) {
            int idx = tid + l * 256;
            int kk = idx >> 6;
            int m  = idx & 63;
            int k  = kb + kk;
            As[kk][m] = (k < kb1) ? g_Lh[k * NR + i0 + m] : 0.f;
            int jj = j0 + m;
            float bv = 0.f;
            if (k < kb1 && jj < 1040)
                bv = (jj < NI) ? g_Faxn[k * NI + jj] : g_Fazn[k * NR + (jj - NI)];
            Bs[kk][m] = bv;
        }
        __syncthreads();
#pragma unroll
        for (int kk = 0; kk < 16; kk++) {
            const float4 ra = *(const float4*)&As[kk][tr * 4];
            const float4 rb = *(const float4*)&Bs[kk][tc * 4];
            acc[0][0] = fmaf(ra.x, rb.x, acc[0][0]); acc[0][1] = fmaf(ra.x, rb.y, acc[0][1]);
            acc[0][2] = fmaf(ra.x, rb.z, acc[0][2]); acc[0][3] = fmaf(ra.x, rb.w, acc[0][3]);
            acc[1][0] = fmaf(ra.y, rb.x, acc[1][0]); acc[1][1] = fmaf(ra.y, rb.y, acc[1][1]);
            acc[1][2] = fmaf(ra.y, rb.z, acc[1][2]); acc[1][3] = fmaf(ra.y, rb.w, acc[1][3]);
            acc[2][0] = fmaf(ra.z, rb.x, acc[2][0]); acc[2][1] = fmaf(ra.z, rb.y, acc[2][1]);
            acc[2][2] = fmaf(ra.z, rb.z, acc[2][2]); acc[2][3] = fmaf(ra.z, rb.w, acc[2][3]);
            acc[3][0] = fmaf(ra.w, rb.x, acc[3][0]); acc[3][1] = fmaf(ra.w, rb.y, acc[3][1]);
            acc[3][2] = fmaf(ra.w, rb.z, acc[3][2]); acc[3][3] = fmaf(ra.w, rb.w, acc[3][3]);
        }
        __syncthreads();
    }
#pragma unroll
    for (int i = 0; i < 4; i++) {
        int row = i0 + tr * 4 + i;
#pragma unroll
        for (int j = 0; j < 4; j++) {
            int jj = j0 + tc * 4 + j;
            if (jj < NI)            atomicAdd(&gwin[row * NI + jj], acc[i][j]);
            else if (jj < NI + NR)  atomicAdd(&gwrec[row * NR + (jj - NI)], acc[i][j]);
        }
    }
}

__device__ __forceinline__ void do_gwout(int cid, float* smem, float* __restrict__ gwout) {
    grid_dep_sync();   // needs g_err / g_Fkzn (step)
    float* s_err = smem;
    const int r = threadIdx.x;
    const int b0 = cid * 20;
    for (int t = r; t < 20 * NO; t += 256) s_err[t] = g_err[b0 * NO + t];
    __syncthreads();
    float acc[NO];
#pragma unroll
    for (int o = 0; o < NO; o++) acc[o] = 0.f;
    for (int bb = 0; bb < 20; bb++) {
        const float f = g_Fkzn[(b0 + bb) * NR + r];
#pragma unroll
        for (int o = 0; o < NO; o++) acc[o] = fmaf(s_err[bb * NO + o], f, acc[o]);
    }
#pragma unroll
    for (int o = 0; o < NO; o++) atomicAdd(&gwout[o * NR + r], acc[o]);
}

#define FMA4(A, C, F) \
    A.x = fmaf(C, F.x, A.x); A.y = fmaf(C, F.y, A.y); \
    A.z = fmaf(C, F.z, A.z); A.w = fmaf(C, F.w, A.w);

// 125 batches per stream block; first 4 batches prefetched PRE-sync (input data)
__device__ __forceinline__ void do_gwin(int sid, float* smem,
                                        const float* __restrict__ Fke_in,
                                        float* __restrict__ gwin) {
    float* s_kL = smem;
    const int t = threadIdx.x;
    const int i  = sid & 255;
    const int b0 = (sid >> 8) * 125;     // chunk 0..7
    const float4* fke = (const float4*)(Fke_in + ((size_t)b0 * NR + i) * NI) + t;
    const size_t stride = (size_t)NR * NI / 4;

    // pre-sync prefetch: Fke is an input, independent of k_step
    float4 p0, p1, p2, p3;
    if (t < 196) {
        p0 = __ldcs(fke + (size_t)0 * stride);
        p1 = __ldcs(fke + (size_t)1 * stride);
        p2 = __ldcs(fke + (size_t)2 * stride);
        p3 = __ldcs(fke + (size_t)3 * stride);
    }
    grid_dep_sync();   // now wait for step's g_kL

    if (t < 125) s_kL[t] = g_kL[(b0 + t) * NR + i];
    __syncthreads();
    if (t >= 196) return;

    float4 a0 = make_float4(0.f, 0.f, 0.f, 0.f);
    float4 a1 = make_float4(0.f, 0.f, 0.f, 0.f);
    float4 a2 = make_float4(0.f, 0.f, 0.f, 0.f);
    float4 a3 = make_float4(0.f, 0.f, 0.f, 0.f);
    {
        float c0 = s_kL[0], c1 = s_kL[1], c2 = s_kL[2], c3 = s_kL[3];
        FMA4(a0, c0, p0) FMA4(a1, c1, p1) FMA4(a2, c2, p2) FMA4(a3, c3, p3)
    }
#pragma unroll 1
    for (int bb = 4; bb < 124; bb += 4) {
        float4 f0 = __ldcs(fke + (size_t)(bb + 0) * stride);
        float4 f1 = __ldcs(fke + (size_t)(bb + 1) * stride);
        float4 f2 = __ldcs(fke + (size_t)(bb + 2) * stride);
        float4 f3 = __ldcs(fke + (size_t)(bb + 3) * stride);
        float c0 = s_kL[bb], c1 = s_kL[bb + 1], c2 = s_kL[bb + 2], c3 = s_kL[bb + 3];
        FMA4(a0, c0, f0) FMA4(a1, c1, f1) FMA4(a2, c2, f2) FMA4(a3, c3, f3)
    }
    {
        float4 f0 = __ldcs(fke + (size_t)124 * stride);
        float c0 = s_kL[124];
        FMA4(a0, c0, f0)
    }
    float* dst = gwin + i * NI + t * 4;
    atomicAdd(dst + 0, (a0.x + a1.x) + (a2.x + a3.x));
    atomicAdd(dst + 1, (a0.y + a1.y) + (a2.y + a3.y));
    atomicAdd(dst + 2, (a0.z + a1.z) + (a2.z + a3.z));
    atomicAdd(dst + 3, (a0.w + a1.w) + (a2.w + a3.w));
}

__device__ __forceinline__ void do_gwrec(int sid, float* smem,
                                         const float* __restrict__ Fke_rec,
                                         float* __restrict__ gwrec) {
    float* s_kL = smem;   // 500 floats (4 rows x 125)
    const int t = threadIdx.x;
    const int i0 = (sid & 63) * 4;
    const int b0 = (sid >> 6) * 125;     // chunk 0..7
    const int li = t >> 6;
    const int jv = t & 63;
    const int i = i0 + li;
    const float4* fke = (const float4*)(Fke_rec + ((size_t)b0 * NR + i) * NR) + jv;
    const size_t stride = (size_t)NR * NR / 4;

    // pre-sync prefetch (all 256 threads valid here)
    float4 p0 = __ldcs(fke + (size_t)0 * stride);
    float4 p1 = __ldcs(fke + (size_t)1 * stride);
    float4 p2 = __ldcs(fke + (size_t)2 * stride);
    float4 p3 = __ldcs(fke + (size_t)3 * stride);
    grid_dep_sync();

    for (int tt = t; tt < 500; tt += 256) {
        int lr = tt / 125, bb = tt % 125;
        s_kL[lr * 125 + bb] = g_kL[(b0 + bb) * NR + i0 + lr];
    }
    __syncthreads();

    const float* kl = s_kL + li * 125;
    float4 a0 = make_float4(0.f, 0.f, 0.f, 0.f);
    float4 a1 = make_float4(0.f, 0.f, 0.f, 0.f);
    float4 a2 = make_float4(0.f, 0.f, 0.f, 0.f);
    float4 a3 = make_float4(0.f, 0.f, 0.f, 0.f);
    {
        float c0 = kl[0], c1 = kl[1], c2 = kl[2], c3 = kl[3];
        FMA4(a0, c0, p0) FMA4(a1, c1, p1) FMA4(a2, c2, p2) FMA4(a3, c3, p3)
    }
#pragma unroll 1
    for (int bb = 4; bb < 124; bb += 4) {
        float4 f0 = __ldcs(fke + (size_t)(bb + 0) * stride);
        float4 f1 = __ldcs(fke + (size_t)(bb + 1) * stride);
        float4 f2 = __ldcs(fke + (size_t)(bb + 2) * stride);
        float4 f3 = __ldcs(fke + (size_t)(bb + 3) * stride);
        float c0 = kl[bb], c1 = kl[bb + 1], c2 = kl[bb + 2], c3 = kl[bb + 3];
        FMA4(a0, c0, f0) FMA4(a1, c1, f1) FMA4(a2, c2, f2) FMA4(a3, c3, f3)
    }
    {
        float4 f0 = __ldcs(fke + (size_t)124 * stride);
        float c0 = kl[124];
        FMA4(a0, c0, f0)
    }
    float* dst = gwrec + i * NR + jv * 4;
    atomicAdd(dst + 0, (a0.x + a1.x) + (a2.x + a3.x));
    atomicAdd(dst + 1, (a0.y + a1.y) + (a2.y + a3.y));
    atomicAdd(dst + 2, (a0.z + a1.z) + (a2.z + a3.z));
    atomicAdd(dst + 3, (a0.w + a1.w) + (a2.w + a3.w));
}

__global__ void __launch_bounds__(256)
k_mega(const float* __restrict__ Fke_in, const float* __restrict__ Fke_rec,
       float* __restrict__ gwin, float* __restrict__ gwrec, float* __restrict__ gwout) {
    __shared__ __align__(16) float smem[2176];
    const int p = blockIdx.x / 9;
    const int l = blockIdx.x % 9;
    if (l == 0) {
        int sid = p;
        if (sid >= N_SPECIAL) { grid_dep_sync(); return; }
        if (sid < N_OUTER) do_outer(sid, smem, gwin, gwrec);
        else               do_gwout(sid - N_OUTER, smem, gwout);
    } else {
        int sid = p * 8 + (l - 1);
        if (sid >= N_STREAM) { grid_dep_sync(); return; }
        if (sid < N_GWIN) do_gwin(sid, smem, Fke_in, gwin);
        else              do_gwrec(sid - N_GWIN, smem, Fke_rec, gwrec);
    }
}

// ---------------- launch ----------------
extern "C" void kernel_launch(void* const* d_in, const int* in_sizes, int n_in,
                              void* d_out, int out_size) {
    const float* x       = (const float*)d_in[0];
    const float* yt      = (const float*)d_in[2];
    const float* w_in    = (const float*)d_in[3];
    const float* w_rec   = (const float*)d_in[4];
    const float* w_out   = (const float*)d_in[5];
    const float* v       = (const float*)d_in[6];
    const float* vo      = (const float*)d_in[7];
    const float* z       = (const float*)d_in[8];
    const float* Faz     = (const float*)d_in[9];
    const float* Fkz     = (const float*)d_in[10];
    const float* Fax     = (const float*)d_in[11];
    const float* Fke_rec = (const float*)d_in[12];
    const float* Fke_in  = (const float*)d_in[13];

    float* out     = (float*)d_out;
    float* yo_o    = out;
    float* gwin_o  = out + NB * NO;
    float* gwrec_o = gwin_o + NR * NI;
    float* gwout_o = gwrec_o + NR * NR;

    k_prep<<<PREP_GRID, 256>>>(x, z, w_in, w_rec, Fax, Faz, gwin_o, gwrec_o, gwout_o);

    // k_step with programmatic dependent launch on k_prep
    {
        cudaLaunchConfig_t cfg = {};
        cfg.gridDim = dim3(NB);
        cfg.blockDim = dim3(NR);
        cfg.stream = 0;
        cudaLaunchAttribute attr[1];
        attr[0].id = cudaLaunchAttributeProgrammaticStreamSerialization;
        attr[0].val.programmaticStreamSerializationAllowed = 1;
        cfg.attrs = attr;
        cfg.numAttrs = 1;
        cudaLaunchKernelEx(&cfg, k_step, v, vo, z, Fkz, w_out, yt, (float*)yo_o);
    }

    // k_mega with programmatic dependent launch on k_step
    {
        cudaLaunchConfig_t cfg = {};
        cfg.gridDim = dim3(MEGA_GRID);
        cfg.blockDim = dim3(256);
        cfg.stream = 0;
        cudaLaunchAttribute attr[1];
        attr[0].id = cudaLaunchAttributeProgrammaticStreamSerialization;
        attr[0].val.programmaticStreamSerializationAllowed = 1;
        cfg.attrs = attr;
        cfg.numAttrs = 1;
        cudaLaunchKernelEx(&cfg, k_mega, Fke_in, Fke_rec, gwin_o, gwrec_o, gwout_o);
    }
}

// round 15
// speedup vs baseline: 1.0776x; 1.0024x over previous
#include <cuda_runtime.h>
#include <cstdint>

// Problem dims
#define NB 1000
#define NI 784
#define NR 256
#define NO 10

#define ALPHA 0.8f
#define KAPPA 0.8f

#define NSPLIT 17          // gemm split-K count (chunks of 64 over K=1040; last=16)

// ---------------- scratch (__device__ globals; no allocation) ----------------
__device__ float g_vpre_p[NSPLIT * NB * NR];  // split-K partials (no atomics)
__device__ float g_kL  [NB * NR];
__device__ float g_Lh  [NB * NR];
__device__ float g_Fazn[NB * NR];
__device__ float g_Fkzn[NB * NR];
__device__ float g_Faxn[NB * NI];
__device__ float g_err [NB * NO];

__device__ __forceinline__ void cp_async4(unsigned int saddr, const float* gptr, int src_bytes) {
    asm volatile("cp.async.ca.shared.global [%0], [%1], 4, %2;"
                 :: "r"(saddr), "l"(gptr), "r"(src_bytes));
}
__device__ __forceinline__ void cp_commit() {
    asm volatile("cp.async.commit_group;");
}
__device__ __forceinline__ void cp_wait(int n) {
    if (n == 0) asm volatile("cp.async.wait_group 0;");
    else        asm volatile("cp.async.wait_group 1;");
}

// ================= PREP KERNEL =================
// blocks [0,544): vpre split-K GEMM, 128x64 tiles, 8x4 micro, cp.async 3-buffer pipeline
// blocks [544,608): aux — zero gw outputs + Faxn + Fazn
#define N_GEMM 544
#define PREP_GRID 608

__global__ void __launch_bounds__(256)
k_prep(const float* __restrict__ x, const float* __restrict__ z,
       const float* __restrict__ w_in, const float* __restrict__ w_rec,
       const float* __restrict__ Fax, const float* __restrict__ Faz,
       float* __restrict__ gwin, float* __restrict__ gwrec, float* __restrict__ gwout) {
#if __CUDA_ARCH__ >= 900
    cudaTriggerProgrammaticLaunchCompletion();
#endif
    if (blockIdx.x >= N_GEMM) {
        // ---- aux role ----
        int idx = (blockIdx.x - N_GEMM) * 256 + threadIdx.x;
        const int stride = (PREP_GRID - N_GEMM) * 256;   // 16384
        const float4 zz = make_float4(0.f, 0.f, 0.f, 0.f);
        for (int i = idx; i < NR * NI / 4; i += stride) ((float4*)gwin)[i] = zz;
        for (int i = idx; i < NR * NR / 4; i += stride) ((float4*)gwrec)[i] = zz;
        for (int i = idx; i < NO * NR / 4; i += stride) ((float4*)gwout)[i] = zz;
        for (int i = idx; i < NB * NI / 4; i += stride) {
            float4 f = ((const float4*)Fax)[i];
            float4 xx = ((const float4*)x)[i];
            float4 o;
            o.x = fmaf(ALPHA, f.x, xx.x); o.y = fmaf(ALPHA, f.y, xx.y);
            o.z = fmaf(ALPHA, f.z, xx.z); o.w = fmaf(ALPHA, f.w, xx.w);
            ((float4*)g_Faxn)[i] = o;
        }
        for (int i = idx; i < NB * NR / 4; i += stride) {
            float4 f = ((const float4*)Faz)[i];
            float4 zo = ((const float4*)z)[i];
            float4 o;
            o.x = fmaf(ALPHA, f.x, zo.x); o.y = fmaf(ALPHA, f.y, zo.y);
            o.z = fmaf(ALPHA, f.z, zo.z); o.w = fmaf(ALPHA, f.w, zo.w);
            ((float4*)g_Fazn)[i] = o;
        }
        return;
    }
    // ---- GEMM role: vpre_p[s][b,r] = sum_{k in chunk s} A[b,k] * W[r,k] ----
    // A = [x | z] (K=1040), W = [w_in | w_rec(diag zeroed)]
    // 128(batch) x 64(rec) tile, 8x4 micro, cp.async 3-buffer / depth-2 lookahead.
    __shared__ __align__(16) float As[3][16][136];
    __shared__ __align__(16) float Ws[3][16][72];
    const int bi = blockIdx.x;
    const int split = bi >> 5;            // 0..16
    const int rem   = bi & 31;
    const int row0 = (rem & 7) * 128;     // batch tile
    const int col0 = (rem >> 3) * 64;     // rec-unit tile
    const int tid = threadIdx.x;
    const int tr = tid >> 4, tc = tid & 15;
    const int kk_l = tid & 15;            // loader k-offset (coalesced across lanes)
    const int m_l  = tid >> 4;            // loader m base (+16 per l)

    const int k_begin = split * 64;
    const int k_end   = (k_begin + 64 < 1040) ? (k_begin + 64) : 1040;
    const int T = (k_end - k_begin) >> 4;  // 4 tiles (last split: 1)

    const unsigned int asA = (unsigned int)__cvta_generic_to_shared(&As[0][0][0]);
    const unsigned int asW = (unsigned int)__cvta_generic_to_shared(&Ws[0][0][0]);

    // tile issue: 12 cp.async of 4B per thread
    auto issue_tile = [&](int tt) {
        const int buf = tt % 3;
        const int k = k_begin + tt * 16 + kk_l;
        const unsigned int aBase = asA + (unsigned int)(((buf * 16 + kk_l) * 136 + m_l) * 4);
        const unsigned int wBase = asW + (unsigned int)(((buf * 16 + kk_l) * 72 + m_l) * 4);
#pragma unroll
        for (int l = 0; l < 8; l++) {
            int m = m_l + l * 16;
            int b = row0 + m;
            int bc = (b < NB) ? b : (NB - 1);     // clamp; src-size 0 masks OOB
            const float* src = (k < NI) ? (x + (size_t)bc * NI + k)
                                        : (z + (size_t)bc * NR + (k - NI));
            cp_async4(aBase + (unsigned int)(l * 16 * 4), src, (b < NB) ? 4 : 0);
        }
#pragma unroll
        for (int l = 0; l < 4; l++) {
            int m = m_l + l * 16;
            int r = col0 + m;
            const float* src;
            int sz = 4;
            if (k < NI) src = w_in + (size_t)r * NI + k;
            else {
                int kr = k - NI;
                src = w_rec + (size_t)r * NR + kr;
                if (kr == r) sz = 0;              // zero diagonal
            }
            cp_async4(wBase + (unsigned int)(l * 16 * 4), src, sz);
        }
        cp_commit();
    };

    issue_tile(0);
    if (T > 1) issue_tile(1);

    float acc[8][4];
#pragma unroll
    for (int i = 0; i < 8; i++)
#pragma unroll
        for (int j = 0; j < 4; j++) acc[i][j] = 0.f;

    for (int t = 0; t < T; t++) {
        cp_wait((t < T - 1) ? 1 : 0);   // tile t landed
        __syncthreads();                // visible to all; buffer (t+2)%3 fully retired
        if (t + 2 < T) issue_tile(t + 2);
        const int buf = t % 3;
#pragma unroll
        for (int kk = 0; kk < 16; kk++) {
            const float4 ra0 = *(const float4*)&As[buf][kk][tr * 8];      // LDS.128
            const float4 ra1 = *(const float4*)&As[buf][kk][tr * 8 + 4];  // LDS.128
            const float4 rb  = *(const float4*)&Ws[buf][kk][tc * 4];      // LDS.128
            const float ra[8] = {ra0.x, ra0.y, ra0.z, ra0.w, ra1.x, ra1.y, ra1.z, ra1.w};
#pragma unroll
            for (int i = 0; i < 8; i++) {
                acc[i][0] = fmaf(ra[i], rb.x, acc[i][0]);
                acc[i][1] = fmaf(ra[i], rb.y, acc[i][1]);
                acc[i][2] = fmaf(ra[i], rb.z, acc[i][2]);
                acc[i][3] = fmaf(ra[i], rb.w, acc[i][3]);
            }
        }
        __syncthreads();                // compute done before buffer reuse next lap
    }
    float* dst = g_vpre_p + (size_t)split * NB * NR;
#pragma unroll
    for (int i = 0; i < 8; i++) {
        int b = row0 + tr * 8 + i;
        if (b < NB) {
            float4 vv = make_float4(acc[i][0], acc[i][1], acc[i][2], acc[i][3]);
            *(float4*)(dst + b * NR + col0 + tc * 4) = vv;
        }
    }
}

// ---------------- per-batch fused step ----------------
__global__ void __launch_bounds__(256)
k_step(const float* __restrict__ v, const float* __restrict__ vo,
       const float* __restrict__ z, const float* __restrict__ Fkz,
       const float* __restrict__ w_out, const float* __restrict__ yt,
       float* __restrict__ yo_out) {
    const int b = blockIdx.x;
    const int r = threadIdx.x;
    __shared__ float s_zn[NR];
    __shared__ float s_err[NO];

    const int ir = b * NR + r;
#if __CUDA_ARCH__ >= 900
    cudaTriggerProgrammaticLaunchCompletion();
#endif
    const float zb = z[ir];
    const float fkzv = Fkz[ir];
    const float vv = v[ir];
#if __CUDA_ARCH__ >= 900
    cudaGridDependencySynchronize();
#endif
    float vpre = 0.f;
#pragma unroll
    for (int s = 0; s < NSPLIT; s++) vpre += g_vpre_p[(size_t)s * NB * NR + ir];

    const float vn = vpre + ALPHA * vv * (1.f - zb);
    const float zn = (vn > 1.f) ? 1.f : 0.f;
    s_zn[r] = zn;
    const float h = fmaxf(0.f, 1.f - fabsf(vn - 1.f));
    g_Fkzn[ir] = KAPPA * fkzv + zn;
    __syncthreads();

    if (r < 32) {
        const int lane = r;
        float part[NO];
#pragma unroll
        for (int o = 0; o < NO; o++) {
            float p = 0.f;
#pragma unroll
            for (int k = 0; k < 8; k++)
                p = fmaf(s_zn[lane + 32 * k], w_out[o * NR + lane + 32 * k], p);
#pragma unroll
            for (int off = 16; off; off >>= 1) p += __shfl_xor_sync(0xffffffffu, p, off);
            part[o] = p;
        }
        if (lane == 0) {
            float vn_o[NO];
            float m = -1e30f;
#pragma unroll
            for (int o = 0; o < NO; o++) {
                vn_o[o] = KAPPA * vo[b * NO + o] + part[o];
                m = fmaxf(m, vn_o[o]);
            }
            float e[NO], s = 0.f;
#pragma unroll
            for (int o = 0; o < NO; o++) { e[o] = expf(vn_o[o] - m); s += e[o]; }
            const float inv = 1.f / s;
#pragma unroll
            for (int o = 0; o < NO; o++) {
                const float yo = e[o] * inv;
                yo_out[b * NO + o] = yo;
                const float er = yo - yt[b * NO + o];
                s_err[o] = er;
                g_err[b * NO + o] = er;
            }
        }
    }
    __syncthreads();

    float L = 0.f;
#pragma unroll
    for (int o = 0; o < NO; o++) L = fmaf(s_err[o], w_out[o * NR + r], L);
    g_kL[ir] = KAPPA * L;
    g_Lh[ir] = L * h;
}

// ================= MEGA KERNEL =================
// Roles (interleaved, period 9 = 1 special + 8 stream):
//   special: 272 outer-GEMM blocks (4 b-splits of 250) + 50 gwout   (322)
//   stream : 2048 gwin blocks + 512 gwrec blocks (b chunks of 125)  (2560)
#define N_OUTER 272
#define N_SPECIAL 322
#define N_GWIN 2048
#define N_STREAM 2560
#define MEGA_GRID 2898     // 322 periods of 9

__device__ __forceinline__ void grid_dep_sync() {
#if __CUDA_ARCH__ >= 900
    cudaGridDependencySynchronize();
#endif
}

__device__ __forceinline__ void do_outer(int oid, float* smem,
                                         float* __restrict__ gwin,
                                         float* __restrict__ gwrec) {
    grid_dep_sync();
    float (*As)[68] = (float(*)[68])smem;
    float (*Bs)[68] = (float(*)[68])(smem + 1088);
    const int split = oid / 68;
    const int rem   = oid % 68;
    const int i0 = (rem & 3) * 64;
    const int j0 = (rem >> 2) * 64;
    const int kb0 = split * 250;
    const int kb1 = kb0 + 250;
    const int tid = threadIdx.x;
    const int tr = tid >> 4, tc = tid & 15;

    float acc[4][4];
#pragma unroll
    for (int i = 0; i < 4; i++)
#pragma unroll
        for (int j = 0; j < 4; j++) acc[i][j] = 0.f;

    for (int kb = kb0; kb < kb1; kb += 16) {
#pragma unroll
        for (int l = 0; l < 4; l++) {
            int idx = tid + l * 256;
            int kk = idx >> 6;
            int m  = idx & 63;
            int k  = kb + kk;
            As[kk][m] = (k < kb1) ? g_Lh[k * NR + i0 + m] : 0.f;
            int jj = j0 + m;
            float bv = 0.f;
            if (k < kb1 && jj < 1040)
                bv = (jj < NI) ? g_Faxn[k * NI + jj] : g_Fazn[k * NR + (jj - NI)];
            Bs[kk][m] = bv;
        }
        __syncthreads();
#pragma unroll
        for (int kk = 0; kk < 16; kk++) {
            const float4 ra = *(const float4*)&As[kk][tr * 4];
            const float4 rb = *(const float4*)&Bs[kk][tc * 4];
            acc[0][0] = fmaf(ra.x, rb.x, acc[0][0]); acc[0][1] = fmaf(ra.x, rb.y, acc[0][1]);
            acc[0][2] = fmaf(ra.x, rb.z, acc[0][2]); acc[0][3] = fmaf(ra.x, rb.w, acc[0][3]);
            acc[1][0] = fmaf(ra.y, rb.x, acc[1][0]); acc[1][1] = fmaf(ra.y, rb.y, acc[1][1]);
            acc[1][2] = fmaf(ra.y, rb.z, acc[1][2]); acc[1][3] = fmaf(ra.y, rb.w, acc[1][3]);
            acc[2][0] = fmaf(ra.z, rb.x, acc[2][0]); acc[2][1] = fmaf(ra.z, rb.y, acc[2][1]);
            acc[2][2] = fmaf(ra.z, rb.z, acc[2][2]); acc[2][3] = fmaf(ra.z, rb.w, acc[2][3]);
            acc[3][0] = fmaf(ra.w, rb.x, acc[3][0]); acc[3][1] = fmaf(ra.w, rb.y, acc[3][1]);
            acc[3][2] = fmaf(ra.w, rb.z, acc[3][2]); acc[3][3] = fmaf(ra.w, rb.w, acc[3][3]);
        }
        __syncthreads();
    }
#pragma unroll
    for (int i = 0; i < 4; i++) {
        int row = i0 + tr * 4 + i;
#pragma unroll
        for (int j = 0; j < 4; j++) {
            int jj = j0 + tc * 4 + j;
            if (jj < NI)            atomicAdd(&gwin[row * NI + jj], acc[i][j]);
            else if (jj < NI + NR)  atomicAdd(&gwrec[row * NR + (jj - NI)], acc[i][j]);
        }
    }
}

__device__ __forceinline__ void do_gwout(int cid, float* smem, float* __restrict__ gwout) {
    grid_dep_sync();
    float* s_err = smem;
    const int r = threadIdx.x;
    const int b0 = cid * 20;
    for (int t = r; t < 20 * NO; t += 256) s_err[t] = g_err[b0 * NO + t];
    __syncthreads();
    float acc[NO];
#pragma unroll
    for (int o = 0; o < NO; o++) acc[o] = 0.f;
    for (int bb = 0; bb < 20; bb++) {
        const float f = g_Fkzn[(b0 + bb) * NR + r];
#pragma unroll
        for (int o = 0; o < NO; o++) acc[o] = fmaf(s_err[bb * NO + o], f, acc[o]);
    }
#pragma unroll
    for (int o = 0; o < NO; o++) atomicAdd(&gwout[o * NR + r], acc[o]);
}

#define FMA4(A, C, F) \
    A.x = fmaf(C, F.x, A.x); A.y = fmaf(C, F.y, A.y); \
    A.z = fmaf(C, F.z, A.z); A.w = fmaf(C, F.w, A.w);

__device__ __forceinline__ void do_gwin(int sid, float* smem,
                                        const float* __restrict__ Fke_in,
                                        float* __restrict__ gwin) {
    float* s_kL = smem;
    const int t = threadIdx.x;
    const int i  = sid & 255;
    const int b0 = (sid >> 8) * 125;
    const float4* fke = (const float4*)(Fke_in + ((size_t)b0 * NR + i) * NI) + t;
    const size_t stride = (size_t)NR * NI / 4;

    float4 p0, p1, p2, p3;
    if (t < 196) {
        p0 = __ldcs(fke + (size_t)0 * stride);
        p1 = __ldcs(fke + (size_t)1 * stride);
        p2 = __ldcs(fke + (size_t)2 * stride);
        p3 = __ldcs(fke + (size_t)3 * stride);
    }
    grid_dep_sync();

    if (t < 125) s_kL[t] = g_kL[(b0 + t) * NR + i];
    __syncthreads();
    if (t >= 196) return;

    float4 a0 = make_float4(0.f, 0.f, 0.f, 0.f);
    float4 a1 = make_float4(0.f, 0.f, 0.f, 0.f);
    float4 a2 = make_float4(0.f, 0.f, 0.f, 0.f);
    float4 a3 = make_float4(0.f, 0.f, 0.f, 0.f);
    {
        float c0 = s_kL[0], c1 = s_kL[1], c2 = s_kL[2], c3 = s_kL[3];
        FMA4(a0, c0, p0) FMA4(a1, c1, p1) FMA4(a2, c2, p2) FMA4(a3, c3, p3)
    }
#pragma unroll 1
    for (int bb = 4; bb < 124; bb += 4) {
        float4 f0 = __ldcs(fke + (size_t)(bb + 0) * stride);
        float4 f1 = __ldcs(fke + (size_t)(bb + 1) * stride);
        float4 f2 = __ldcs(fke + (size_t)(bb + 2) * stride);
        float4 f3 = __ldcs(fke + (size_t)(bb + 3) * stride);
        float c0 = s_kL[bb], c1 = s_kL[bb + 1], c2 = s_kL[bb + 2], c3 = s_kL[bb + 3];
        FMA4(a0, c0, f0) FMA4(a1, c1, f1) FMA4(a2, c2, f2) FMA4(a3, c3, f3)
    }
    {
        float4 f0 = __ldcs(fke + (size_t)124 * stride);
        float c0 = s_kL[124];
        FMA4(a0, c0, f0)
    }
    float* dst = gwin + i * NI + t * 4;
    atomicAdd(dst + 0, (a0.x + a1.x) + (a2.x + a3.x));
    atomicAdd(dst + 1, (a0.y + a1.y) + (a2.y + a3.y));
    atomicAdd(dst + 2, (a0.z + a1.z) + (a2.z + a3.z));
    atomicAdd(dst + 3, (a0.w + a1.w) + (a2.w + a3.w));
}

__device__ __forceinline__ void do_gwrec(int sid, float* smem,
                                         const float* __restrict__ Fke_rec,
                                         float* __restrict__ gwrec) {
    float* s_kL = smem;   // 500 floats (4 rows x 125)
    const int t = threadIdx.x;
    const int i0 = (sid & 63) * 4;
    const int b0 = (sid >> 6) * 125;
    const int li = t >> 6;
    const int jv = t & 63;
    const int i = i0 + li;
    const float4* fke = (const float4*)(Fke_rec + ((size_t)b0 * NR + i) * NR) + jv;
    const size_t stride = (size_t)NR * NR / 4;

    float4 p0 = __ldcs(fke + (size_t)0 * stride);
    float4 p1 = __ldcs(fke + (size_t)1 * stride);
    float4 p2 = __ldcs(fke + (size_t)2 * stride);
    float4 p3 = __ldcs(fke + (size_t)3 * stride);
    grid_dep_sync();

    for (int tt = t; tt < 500; tt += 256) {
        int lr = tt / 125, bb = tt % 125;
        s_kL[lr * 125 + bb] = g_kL[(b0 + bb) * NR + i0 + lr];
    }
    __syncthreads();

    const float* kl = s_kL + li * 125;
    float4 a0 = make_float4(0.f, 0.f, 0.f, 0.f);
    float4 a1 = make_float4(0.f, 0.f, 0.f, 0.f);
    float4 a2 = make_float4(0.f, 0.f, 0.f, 0.f);
    float4 a3 = make_float4(0.f, 0.f, 0.f, 0.f);
    {
        float c0 = kl[0], c1 = kl[1], c2 = kl[2], c3 = kl[3];
        FMA4(a0, c0, p0) FMA4(a1, c1, p1) FMA4(a2, c2, p2) FMA4(a3, c3, p3)
    }
#pragma unroll 1
    for (int bb = 4; bb < 124; bb += 4) {
        float4 f0 = __ldcs(fke + (size_t)(bb + 0) * stride);
        float4 f1 = __ldcs(fke + (size_t)(bb + 1) * stride);
        float4 f2 = __ldcs(fke + (size_t)(bb + 2) * stride);
        float4 f3 = __ldcs(fke + (size_t)(bb + 3) * stride);
        float c0 = kl[bb], c1 = kl[bb + 1], c2 = kl[bb + 2], c3 = kl[bb + 3];
        FMA4(a0, c0, f0) FMA4(a1, c1, f1) FMA4(a2, c2, f2) FMA4(a3, c3, f3)
    }
    {
        float4 f0 = __ldcs(fke + (size_t)124 * stride);
        float c0 = kl[124];
        FMA4(a0, c0, f0)
    }
    float* dst = gwrec + i * NR + jv * 4;
    atomicAdd(dst + 0, (a0.x + a1.x) + (a2.x + a3.x));
    atomicAdd(dst + 1, (a0.y + a1.y) + (a2.y + a3.y));
    atomicAdd(dst + 2, (a0.z + a1.z) + (a2.z + a3.z));
    atomicAdd(dst + 3, (a0.w + a1.w) + (a2.w + a3.w));
}

__global__ void __launch_bounds__(256)
k_mega(const float* __restrict__ Fke_in, const float* __restrict__ Fke_rec,
       float* __restrict__ gwin, float* __restrict__ gwrec, float* __restrict__ gwout) {
    __shared__ __align__(16) float smem[2176];
    const int p = blockIdx.x / 9;
    const int l = blockIdx.x % 9;
    if (l == 0) {
        int sid = p;
        if (sid >= N_SPECIAL) { grid_dep_sync(); return; }
        if (sid < N_OUTER) do_outer(sid, smem, gwin, gwrec);
        else               do_gwout(sid - N_OUTER, smem, gwout);
    } else {
        int sid = p * 8 + (l - 1);
        if (sid >= N_STREAM) { grid_dep_sync(); return; }
        if (sid < N_GWIN) do_gwin(sid, smem, Fke_in, gwin);
        else              do_gwrec(sid - N_GWIN, smem, Fke_rec, gwrec);
    }
}

// ---------------- launch ----------------
extern "C" void kernel_launch(void* const* d_in, const int* in_sizes, int n_in,
                              void* d_out, int out_size) {
    const float* x       = (const float*)d_in[0];
    const float* yt      = (const float*)d_in[2];
    const float* w_in    = (const float*)d_in[3];
    const float* w_rec   = (const float*)d_in[4];
    const float* w_out   = (const float*)d_in[5];
    const float* v       = (const float*)d_in[6];
    const float* vo      = (const float*)d_in[7];
    const float* z       = (const float*)d_in[8];
    const float* Faz     = (const float*)d_in[9];
    const float* Fkz     = (const float*)d_in[10];
    const float* Fax     = (const float*)d_in[11];
    const float* Fke_rec = (const float*)d_in[12];
    const float* Fke_in  = (const float*)d_in[13];

    float* out     = (float*)d_out;
    float* yo_o    = out;
    float* gwin_o  = out + NB * NO;
    float* gwrec_o = gwin_o + NR * NI;
    float* gwout_o = gwrec_o + NR * NR;

    k_prep<<<PREP_GRID, 256>>>(x, z, w_in, w_rec, Fax, Faz, gwin_o, gwrec_o, gwout_o);

    {
        cudaLaunchConfig_t cfg = {};
        cfg.gridDim = dim3(NB);
        cfg.blockDim = dim3(NR);
        cfg.stream = 0;
        cudaLaunchAttribute attr[1];
        attr[0].id = cudaLaunchAttributeProgrammaticStreamSerialization;
        attr[0].val.programmaticStreamSerializationAllowed = 1;
        cfg.attrs = attr;
        cfg.numAttrs = 1;
        cudaLaunchKernelEx(&cfg, k_step, v, vo, z, Fkz, w_out, yt, (float*)yo_o);
    }
    {
        cudaLaunchConfig_t cfg = {};
        cfg.gridDim = dim3(MEGA_GRID);
        cfg.blockDim = dim3(256);
        cfg.stream = 0;
        cudaLaunchAttribute attr[1];
        attr[0].id = cudaLaunchAttributeProgrammaticStreamSerialization;
        attr[0].val.programmaticStreamSerializationAllowed = 1;
        cfg.attrs = attr;
        cfg.numAttrs = 1;
        cudaLaunchKernelEx(&cfg, k_mega, Fke_in, Fke_rec, gwin_o, gwrec_o, gwout_o);
    }
}